// round 1
// baseline (speedup 1.0000x reference)
#include <cuda_runtime.h>
#include <cuda_bf16.h>
#include <cstdint>

// Problem constants
#define LNUM 2
#define SS   1024
#define MM   2048      // B*S tokens
#define NST  16        // SSM state dim
#define NCH  32        // scan chunks
#define TCH  32        // steps per chunk

#define FLAG_SOFTPLUS 1
#define FLAG_FLIP     2

// ---------------- scratch (static device memory; no allocation) ----------------
#define OFF_XP    0
#define OFF_XN    (OFF_XP   + MM*512)
#define OFF_XZ    (OFF_XN   + 2*MM*256)
#define OFF_XC    (OFF_XZ   + 2*MM*1024)
#define OFF_DBL   (OFF_XC   + 2*MM*512)
#define OFF_DT    (OFF_DBL  + 2*MM*48)
#define OFF_YG    (OFF_DT   + 2*MM*512)
#define OFF_YCAT  (OFF_YG   + 2*MM*512)
#define OFF_H0    (OFF_YCAT + MM*512)
#define OFF_H1    (OFF_H0   + MM*512)
#define OFF_P     (OFF_H1   + MM*512)
#define OFF_HEND  (OFF_P    + 2*2*NCH*NST*512)
#define OFF_HINIT (OFF_HEND + 2*2*NCH*NST*512)
#define SCRATCH_TOTAL (OFF_HINIT + 2*2*NCH*NST*512)

__device__ float g_scratch[SCRATCH_TOTAL];

// ---------------- GEMM: C = A(M x K) @ W(N x K)^T (+bias)(+softplus)(+resid, flip-store) ----
// BM=128, BN=64, BK=16, 256 threads, 8x4 per thread. blockIdx.z = direction batch.
__global__ __launch_bounds__(256) void gemm_kernel(
    const float* __restrict__ A, int lda, long long sAz,
    const float* __restrict__ W, int ldw, long long sWz,
    float* __restrict__ C, int ldc, long long sCz, int colOffPerZ,
    const float* __restrict__ bias, int sBiasZ,
    const float* __restrict__ resid,
    int N_, int K_, int flags)
{
    const int z  = blockIdx.z;
    const float* Ab = A + (size_t)z * sAz;
    const float* Wb = W + (size_t)z * sWz;
    const int m0 = blockIdx.y * 128;
    const int n0 = blockIdx.x * 64;

    __shared__ float As[16][132];
    __shared__ float Ws[16][68];

    float acc[8][4];
#pragma unroll
    for (int i = 0; i < 8; i++)
#pragma unroll
        for (int j = 0; j < 4; j++) acc[i][j] = 0.f;

    const int tid = threadIdx.x;
    const int tx = tid & 15, ty = tid >> 4;

    for (int k0 = 0; k0 < K_; k0 += 16) {
#pragma unroll
        for (int i = 0; i < 2; i++) {
            int lin = tid + i * 256;
            int m = lin >> 2, kq = (lin & 3) << 2;
            const float4 v = *reinterpret_cast<const float4*>(
                &Ab[(size_t)(m0 + m) * lda + k0 + kq]);
            As[kq + 0][m] = v.x; As[kq + 1][m] = v.y;
            As[kq + 2][m] = v.z; As[kq + 3][m] = v.w;
        }
        {
            int n = tid >> 2, kq = (tid & 3) << 2;
            float4 v = make_float4(0.f, 0.f, 0.f, 0.f);
            if (n0 + n < N_)
                v = *reinterpret_cast<const float4*>(
                    &Wb[(size_t)(n0 + n) * ldw + k0 + kq]);
            Ws[kq + 0][n] = v.x; Ws[kq + 1][n] = v.y;
            Ws[kq + 2][n] = v.z; Ws[kq + 3][n] = v.w;
        }
        __syncthreads();
#pragma unroll
        for (int k = 0; k < 16; k++) {
            float4 a0 = *reinterpret_cast<const float4*>(&As[k][ty * 8]);
            float4 a1 = *reinterpret_cast<const float4*>(&As[k][ty * 8 + 4]);
            float4 wv = *reinterpret_cast<const float4*>(&Ws[k][tx * 4]);
            float av[8] = {a0.x, a0.y, a0.z, a0.w, a1.x, a1.y, a1.z, a1.w};
            float wf[4] = {wv.x, wv.y, wv.z, wv.w};
#pragma unroll
            for (int i = 0; i < 8; i++)
#pragma unroll
                for (int j = 0; j < 4; j++)
                    acc[i][j] = fmaf(av[i], wf[j], acc[i][j]);
        }
        __syncthreads();
    }

    const int coff = colOffPerZ * z;
#pragma unroll
    for (int i = 0; i < 8; i++) {
        int m = m0 + ty * 8 + i;
        int r = m;
        if ((flags & FLAG_FLIP) && z == 1)
            r = (m & ~(SS - 1)) + ((SS - 1) - (m & (SS - 1)));
        float* crow = C + (size_t)z * sCz + (size_t)r * ldc + coff;
#pragma unroll
        for (int j = 0; j < 4; j++) {
            int n = n0 + tx * 4 + j;
            if (n < N_) {
                float v = acc[i][j];
                if (bias) v += bias[z * sBiasZ + n];
                if (flags & FLAG_SOFTPLUS)
                    v = (v > 20.f) ? v : log1pf(__expf(v));
                if (resid) v += resid[(size_t)r * ldc + coff + n];
                crow[n] = v;
            }
        }
    }
}

// ---------------- LayerNorm (optionally slice cols + flip S for z==1) ----------------
__device__ __forceinline__ void block_reduce_2(float& s1, float& s2)
{
    __shared__ float sh1[8], sh2[8];
#pragma unroll
    for (int o = 16; o > 0; o >>= 1) {
        s1 += __shfl_xor_sync(0xffffffffu, s1, o);
        s2 += __shfl_xor_sync(0xffffffffu, s2, o);
    }
    int lane = threadIdx.x & 31, wid = threadIdx.x >> 5;
    if (lane == 0) { sh1[wid] = s1; sh2[wid] = s2; }
    __syncthreads();
    if (threadIdx.x == 0) {
        float a = 0.f, b = 0.f;
#pragma unroll
        for (int i = 0; i < 8; i++) { a += sh1[i]; b += sh2[i]; }
        sh1[0] = a; sh2[0] = b;
    }
    __syncthreads();
    s1 = sh1[0]; s2 = sh2[0];
}

__global__ __launch_bounds__(256) void ln_kernel(
    const float* __restrict__ src, int ldsrc, int colOffPerZ, int flipz,
    const float* __restrict__ g, const float* __restrict__ bta, int gbStrideZ,
    float* __restrict__ dst, int lddst, long long dstStrideZ, int Dvec)
{
    const int m = blockIdx.x, z = blockIdx.y;
    int srow = m;
    if (flipz && z == 1)
        srow = (m & ~(SS - 1)) + ((SS - 1) - (m & (SS - 1)));
    const float* sp = src + (size_t)srow * ldsrc + colOffPerZ * z;
    const int tid = threadIdx.x;

    float v0 = sp[tid];
    float v1 = (Dvec > 256) ? sp[tid + 256] : 0.f;
    float s1 = v0 + v1, s2 = v0 * v0 + v1 * v1;
    block_reduce_2(s1, s2);

    const float invD = 1.f / (float)Dvec;
    float mean = s1 * invD;
    float var  = s2 * invD - mean * mean;
    float inv  = rsqrtf(var + 1e-5f);

    const float* gz = g + z * gbStrideZ;
    const float* bz = bta + z * gbStrideZ;
    float* dp = dst + (size_t)z * dstStrideZ + (size_t)m * lddst;
    dp[tid] = (v0 - mean) * inv * gz[tid] + bz[tid];
    if (Dvec > 256)
        dp[tid + 256] = (v1 - mean) * inv * gz[tid + 256] + bz[tid + 256];
}

// ---------------- causal depthwise conv (K=4) + SiLU ----------------
__global__ __launch_bounds__(256) void conv_silu_kernel(
    const float* __restrict__ xz,   // [2][MM][1024], cols 0..511 are xc-raw
    const float* __restrict__ cW,   // [2][512][4]
    const float* __restrict__ cB,   // [2][512]
    float* __restrict__ xc)         // [2][MM][512]
{
    int idx = blockIdx.x * 256 + threadIdx.x;      // < 2*MM*512 = 2^21
    int d   = idx & 511;
    int row = (idx >> 9) & (MM - 1);
    int z   = idx >> 20;
    int s   = row & (SS - 1);
    int bs0 = row - s;                              // batch base row

    const float4 wv = *reinterpret_cast<const float4*>(&cW[((size_t)z * 512 + d) * 4]);
    const float w[4] = {wv.x, wv.y, wv.z, wv.w};
    float acc = cB[z * 512 + d];
    const float* xzz = xz + (size_t)z * MM * 1024;
#pragma unroll
    for (int k = 0; k < 4; k++) {
        int sp = s - 3 + k;
        if (sp >= 0) acc += w[k] * xzz[(size_t)(bs0 + sp) * 1024 + d];
    }
    float sig = 1.f / (1.f + __expf(-acc));
    xc[(size_t)z * MM * 512 + (size_t)row * 512 + d] = acc * sig;
}

// ---------------- chunked SSM scan ----------------
// Phase 1: per (z,b,chunk,d): P[n] = prod exp(dt*A[n]); hend[n] = chunk scan from h=0.
__global__ __launch_bounds__(256) void scan_phase1(
    const float* __restrict__ dtp,   // [2][MM][512]
    const float* __restrict__ xcp,   // [2][MM][512]
    const float* __restrict__ dblp,  // [2][MM][48] (B at 16..31)
    const float* __restrict__ A_log_l, // [2][512][16]
    float* __restrict__ P, float* __restrict__ hend)
{
    const int chunk = blockIdx.x >> 1;
    const int dg    = blockIdx.x & 1;
    const int b     = blockIdx.y, z = blockIdx.z;
    const int d     = dg * 256 + threadIdx.x;

    __shared__ float sB[TCH][NST];
    const float* dbl_z = dblp + (size_t)z * MM * 48;
    const int base = b * SS + chunk * TCH;
    for (int i = threadIdx.x; i < TCH * NST; i += 256) {
        int t = i >> 4, n = i & 15;
        sB[t][n] = dbl_z[(size_t)(base + t) * 48 + 16 + n];
    }
    __syncthreads();

    float a[NST];
    const float* al = A_log_l + ((size_t)z * 512 + d) * NST;
#pragma unroll
    for (int n = 0; n < NST; n++) a[n] = -expf(al[n]);

    float h[NST], Pr[NST];
#pragma unroll
    for (int n = 0; n < NST; n++) { h[n] = 0.f; Pr[n] = 1.f; }

    const float* dtz = dtp + (size_t)z * MM * 512;
    const float* xcz = xcp + (size_t)z * MM * 512;
    for (int t = 0; t < TCH; t++) {
        int row = base + t;
        float dtv = dtz[(size_t)row * 512 + d];
        float xv  = xcz[(size_t)row * 512 + d];
        float dx  = dtv * xv;
#pragma unroll
        for (int n = 0; n < NST; n++) {
            float dA = __expf(dtv * a[n]);
            h[n]  = fmaf(dA, h[n], dx * sB[t][n]);
            Pr[n] *= dA;
        }
    }
    size_t ob = ((((size_t)z * 2 + b) * NCH + chunk) * NST) * 512 + d;
#pragma unroll
    for (int n = 0; n < NST; n++) {
        P[ob + (size_t)n * 512]    = Pr[n];
        hend[ob + (size_t)n * 512] = h[n];
    }
}

// Phase 2: sequential stitch across 32 chunks per (z,b,d). 2048 threads.
__global__ __launch_bounds__(256) void scan_phase2(
    const float* __restrict__ P, const float* __restrict__ hend,
    float* __restrict__ hinit)
{
    int idx = blockIdx.x * 256 + threadIdx.x;   // 0..2047
    int z = idx >> 10, b = (idx >> 9) & 1, d = idx & 511;
    float h0[NST];
#pragma unroll
    for (int n = 0; n < NST; n++) h0[n] = 0.f;
    for (int c = 0; c < NCH; c++) {
        size_t ob = ((((size_t)z * 2 + b) * NCH + c) * NST) * 512 + d;
#pragma unroll
        for (int n = 0; n < NST; n++) {
            hinit[ob + (size_t)n * 512] = h0[n];
            h0[n] = fmaf(P[ob + (size_t)n * 512], h0[n], hend[ob + (size_t)n * 512]);
        }
    }
}

// Phase 3: replay with correct init; y = (scan + xc*Dp) * silu(z-gate)
__global__ __launch_bounds__(256) void scan_phase3(
    const float* __restrict__ dtp, const float* __restrict__ xcp,
    const float* __restrict__ dblp, const float* __restrict__ A_log_l,
    const float* __restrict__ hinit,
    const float* __restrict__ xzp,  // [2][MM][1024], z-gate at cols 512..1023
    const float* __restrict__ Dp_l, // [2][512]
    float* __restrict__ yg)         // [2][MM][512]
{
    const int chunk = blockIdx.x >> 1;
    const int dg    = blockIdx.x & 1;
    const int b     = blockIdx.y, z = blockIdx.z;
    const int d     = dg * 256 + threadIdx.x;

    __shared__ float sBC[TCH][32];   // B at [t][0..15], C at [t][16..31]
    const float* dbl_z = dblp + (size_t)z * MM * 48;
    const int base = b * SS + chunk * TCH;
    for (int i = threadIdx.x; i < TCH * 32; i += 256) {
        int t = i >> 5, n = i & 31;
        sBC[t][n] = dbl_z[(size_t)(base + t) * 48 + 16 + n];
    }
    __syncthreads();

    float a[NST];
    const float* al = A_log_l + ((size_t)z * 512 + d) * NST;
#pragma unroll
    for (int n = 0; n < NST; n++) a[n] = -expf(al[n]);

    float h[NST];
    {
        size_t ob = ((((size_t)z * 2 + b) * NCH + chunk) * NST) * 512 + d;
#pragma unroll
        for (int n = 0; n < NST; n++) h[n] = hinit[ob + (size_t)n * 512];
    }
    const float Dv = Dp_l[z * 512 + d];
    const float* dtz = dtp + (size_t)z * MM * 512;
    const float* xcz = xcp + (size_t)z * MM * 512;
    const float* xzz = xzp + (size_t)z * MM * 1024;
    float* ygz = yg + (size_t)z * MM * 512;

    for (int t = 0; t < TCH; t++) {
        int row = base + t;
        float dtv = dtz[(size_t)row * 512 + d];
        float xv  = xcz[(size_t)row * 512 + d];
        float dx  = dtv * xv;
        float y = 0.f;
#pragma unroll
        for (int n = 0; n < NST; n++) {
            float dA = __expf(dtv * a[n]);
            h[n] = fmaf(dA, h[n], dx * sBC[t][n]);
            y = fmaf(h[n], sBC[t][16 + n], y);
        }
        float yfull = fmaf(xv, Dv, y);
        float zv = xzz[(size_t)row * 1024 + 512 + d];
        float sig = 1.f / (1.f + __expf(-zv));
        ygz[(size_t)row * 512 + d] = yfull * zv * sig;
    }
}

// ---------------- host orchestration ----------------
extern "C" void kernel_launch(void* const* d_in, const int* in_sizes, int n_in,
                              void* d_out, int out_size)
{
    const float* x      = (const float*)d_in[0];
    const float* ln_g   = (const float*)d_in[1];
    const float* ln_b   = (const float*)d_in[2];
    const float* inW    = (const float*)d_in[3];
    const float* convW  = (const float*)d_in[4];
    const float* convB  = (const float*)d_in[5];
    const float* xprojW = (const float*)d_in[6];
    const float* dtW    = (const float*)d_in[7];
    const float* dtB    = (const float*)d_in[8];
    const float* A_log  = (const float*)d_in[9];
    const float* Dp     = (const float*)d_in[10];
    const float* outW   = (const float*)d_in[11];
    const float* ipW    = (const float*)d_in[12];
    const float* ipB    = (const float*)d_in[13];
    const float* opW    = (const float*)d_in[14];
    const float* opB    = (const float*)d_in[15];
    const float* fln_g  = (const float*)d_in[16];
    const float* fln_b  = (const float*)d_in[17];

    float* scratch = nullptr;
    cudaGetSymbolAddress((void**)&scratch, g_scratch);
    float* xp   = scratch + OFF_XP;
    float* xn   = scratch + OFF_XN;
    float* xzb  = scratch + OFF_XZ;
    float* xc   = scratch + OFF_XC;
    float* dbl  = scratch + OFF_DBL;
    float* dtb  = scratch + OFF_DT;
    float* yg   = scratch + OFF_YG;
    float* ycat = scratch + OFF_YCAT;
    float* hbuf[2] = { scratch + OFF_H0, scratch + OFF_H1 };
    float* Pb   = scratch + OFF_P;
    float* heb  = scratch + OFF_HEND;
    float* hib  = scratch + OFF_HINIT;

    const float* hin = x;
    for (int l = 0; l < LNUM; l++) {
        const size_t l2 = (size_t)l * 2;

        // xp = hin @ ipW_l^T + ipB_l              (M=2048, N=512, K=512)
        gemm_kernel<<<dim3(8, 16, 1), 256>>>(
            hin, 512, 0, ipW + (size_t)l * 512 * 512, 512, 0,
            xp, 512, 0, 0, ipB + l * 512, 0, nullptr, 512, 512, 0);

        // per-dir LN over 256 (dir1 reads cols 256.. with flipped S)
        ln_kernel<<<dim3(MM, 2), 256>>>(
            xp, 512, 256, 1, ln_g + l2 * 256, ln_b + l2 * 256, 256,
            xn, 256, (long long)MM * 256, 256);

        // xz = xn @ inW^T                          (N=1024, K=256), both dirs
        gemm_kernel<<<dim3(16, 16, 2), 256>>>(
            xn, 256, (long long)MM * 256,
            inW + l2 * 1024 * 256, 256, (long long)1024 * 256,
            xzb, 1024, (long long)MM * 1024, 0, nullptr, 0, nullptr, 1024, 256, 0);

        // causal dwconv + silu on xz[..,:512]
        conv_silu_kernel<<<(2 * MM * 512) / 256, 256>>>(
            xzb, convW + l2 * 512 * 4, convB + l2 * 512, xc);

        // dbl = xc @ xprojW^T                      (N=48, K=512)
        gemm_kernel<<<dim3(1, 16, 2), 256>>>(
            xc, 512, (long long)MM * 512,
            xprojW + l2 * 48 * 512, 512, (long long)48 * 512,
            dbl, 48, (long long)MM * 48, 0, nullptr, 0, nullptr, 48, 512, 0);

        // dt = softplus(dbl[:,:16] @ dtW^T + dtB)  (N=512, K=16)
        gemm_kernel<<<dim3(8, 16, 2), 256>>>(
            dbl, 48, (long long)MM * 48,
            dtW + l2 * 512 * 16, 16, (long long)512 * 16,
            dtb, 512, (long long)MM * 512, 0,
            dtB + l2 * 512, 512, nullptr, 512, 16, FLAG_SOFTPLUS);

        // chunked scan
        scan_phase1<<<dim3(NCH * 2, 2, 2), 256>>>(
            dtb, xc, dbl, A_log + l2 * 512 * NST, Pb, heb);
        scan_phase2<<<8, 256>>>(Pb, heb, hib);
        scan_phase3<<<dim3(NCH * 2, 2, 2), 256>>>(
            dtb, xc, dbl, A_log + l2 * 512 * NST, hib, xzb, Dp + l2 * 512, yg);

        // per-dir out: ycat[:, z*256..] = u + yg @ outW^T   (N=256, K=512), dir1 flip-store
        gemm_kernel<<<dim3(4, 16, 2), 256>>>(
            yg, 512, (long long)MM * 512,
            outW + l2 * 256 * 512, 512, (long long)256 * 512,
            ycat, 512, 0, 256, nullptr, 0, xp, 256, 512, FLAG_FLIP);

        // h_next = ycat @ opW^T + opB              (N=512, K=512)
        float* hout = hbuf[l & 1];
        gemm_kernel<<<dim3(8, 16, 1), 256>>>(
            ycat, 512, 0, opW + (size_t)l * 512 * 512, 512, 0,
            hout, 512, 0, 0, opB + l * 512, 0, nullptr, 512, 512, 0);
        hin = hout;
    }

    // final LN over 512 -> d_out
    ln_kernel<<<dim3(MM, 1), 256>>>(
        hin, 512, 0, 0, fln_g, fln_b, 0,
        (float*)d_out, 512, 0, 512);
}

// round 2
// speedup vs baseline: 1.3036x; 1.3036x over previous
#include <cuda_runtime.h>
#include <cuda_bf16.h>
#include <cstdint>

// Problem constants
#define LNUM 2
#define SS   1024
#define MM   2048      // B*S tokens
#define NST  16        // SSM state dim
#define NCH  32        // scan chunks
#define TCH  32        // steps per chunk

#define FLAG_SOFTPLUS 1
#define FLAG_FLIP     2

// ---------------- scratch (static device memory; no allocation) ----------------
#define OFF_XP    0
#define OFF_XN    (OFF_XP   + MM*512)
#define OFF_XZ    (OFF_XN   + 2*MM*256)
#define OFF_XC    (OFF_XZ   + 2*MM*1024)
#define OFF_DBL   (OFF_XC   + 2*MM*512)
#define OFF_DT    (OFF_DBL  + 2*MM*48)
#define OFF_YG    (OFF_DT   + 2*MM*512)
#define OFF_YCAT  (OFF_YG   + 2*MM*512)
#define OFF_H0    (OFF_YCAT + MM*512)
#define OFF_H1    (OFF_H0   + MM*512)
#define OFF_P     (OFF_H1   + MM*512)
#define OFF_HEND  (OFF_P    + 2*2*NCH*NST*512)
#define OFF_HINIT (OFF_HEND + 2*2*NCH*NST*512)
#define SCRATCH_TOTAL (OFF_HINIT + 2*2*NCH*NST*512)

__device__ float g_scratch[SCRATCH_TOTAL];

// pack float into both halves of a 64-bit reg
#define PACK_DUP(dst, s) asm("mov.b64 %0, {%1, %1};" : "=l"(dst) : "f"(s))
#define FMA2(acc, a, b)  asm("fma.rn.f32x2 %0, %1, %2, %0;" : "+l"(acc) : "l"(a), "l"(b))
#define UNPACK2(lo, hi, v) asm("mov.b64 {%0, %1}, %2;" : "=f"(lo), "=f"(hi) : "l"(v))

// ---------------- GEMM via packed f32x2 ----------------
// C = A(M x K) @ W(N x K)^T (+bias)(+softplus)(+resid, flip-store)
// Tile: BMT x 64, BK=16, 256 threads. Per-thread: (BMT/16) m x 4 n.
// Accumulators packed in pairs along m (f32x2).
template<int BMT>
__global__ __launch_bounds__(256, 2) void gemm2_kernel(
    const float* __restrict__ A, int lda, long long sAz,
    const float* __restrict__ W, int ldw, long long sWz,
    float* __restrict__ C, int ldc, long long sCz, int colOffPerZ,
    const float* __restrict__ bias, int sBiasZ,
    const float* __restrict__ resid,
    int N_, int K_, int flags)
{
    constexpr int MT = BMT / 16;   // 8 or 4 rows per thread
    constexpr int MP = MT / 2;     // packed pairs
    constexpr int AL = BMT + 4;    // padded A-tile row
    constexpr int NA = BMT / 64;   // A-frag float4 count per thread (2 or 1)

    const int z  = blockIdx.z;
    const float* Ab = A + (size_t)z * sAz;
    const float* Wb = W + (size_t)z * sWz;
    const int m0 = blockIdx.y * BMT;
    const int n0 = blockIdx.x * 64;

    __shared__ __align__(16) float As[16][AL];
    __shared__ __align__(16) float Ws[16][68];

    unsigned long long acc[MP][4];
#pragma unroll
    for (int i = 0; i < MP; i++)
#pragma unroll
        for (int j = 0; j < 4; j++) acc[i][j] = 0ULL;

    const int tid = threadIdx.x;
    const int tx = tid & 15, ty = tid >> 4;

    // staging registers for prefetch
    float4 aFrag[NA];
    float4 wFrag;
    const int am[NA > 1 ? NA : 1] = {0};
    (void)am;

    // ---- load first chunk into regs ----
    {
#pragma unroll
        for (int i = 0; i < NA; i++) {
            int lin = tid + i * 256;
            int m = lin >> 2, kq = (lin & 3) << 2;
            aFrag[i] = *reinterpret_cast<const float4*>(
                &Ab[(size_t)(m0 + m) * lda + kq]);
        }
        int n = tid >> 2, kq = (tid & 3) << 2;
        wFrag = make_float4(0.f, 0.f, 0.f, 0.f);
        if (n0 + n < N_)
            wFrag = *reinterpret_cast<const float4*>(
                &Wb[(size_t)(n0 + n) * ldw + kq]);
    }

    for (int k0 = 0; k0 < K_; k0 += 16) {
        // ---- store staged frags to smem ----
#pragma unroll
        for (int i = 0; i < NA; i++) {
            int lin = tid + i * 256;
            int m = lin >> 2, kq = (lin & 3) << 2;
            As[kq + 0][m] = aFrag[i].x; As[kq + 1][m] = aFrag[i].y;
            As[kq + 2][m] = aFrag[i].z; As[kq + 3][m] = aFrag[i].w;
        }
        {
            int n = tid >> 2, kq = (tid & 3) << 2;
            Ws[kq + 0][n] = wFrag.x; Ws[kq + 1][n] = wFrag.y;
            Ws[kq + 2][n] = wFrag.z; Ws[kq + 3][n] = wFrag.w;
        }
        __syncthreads();

        // ---- prefetch next chunk (overlaps with compute) ----
        if (k0 + 16 < K_) {
#pragma unroll
            for (int i = 0; i < NA; i++) {
                int lin = tid + i * 256;
                int m = lin >> 2, kq = (lin & 3) << 2;
                aFrag[i] = *reinterpret_cast<const float4*>(
                    &Ab[(size_t)(m0 + m) * lda + k0 + 16 + kq]);
            }
            int n = tid >> 2, kq = (tid & 3) << 2;
            wFrag = make_float4(0.f, 0.f, 0.f, 0.f);
            if (n0 + n < N_)
                wFrag = *reinterpret_cast<const float4*>(
                    &Wb[(size_t)(n0 + n) * ldw + k0 + 16 + kq]);
        }

        // ---- compute 16 k-steps ----
#pragma unroll
        for (int k = 0; k < 16; k++) {
            unsigned long long ap[MP];
            {
                ulonglong2 q0 = *reinterpret_cast<const ulonglong2*>(&As[k][ty * MT]);
                ap[0] = q0.x; ap[1] = q0.y;
                if (MP == 4) {
                    ulonglong2 q1 = *reinterpret_cast<const ulonglong2*>(&As[k][ty * MT + 4]);
                    ap[2] = q1.x; ap[3] = q1.y;
                }
            }
            float4 wv = *reinterpret_cast<const float4*>(&Ws[k][tx * 4]);
            unsigned long long wd[4];
            PACK_DUP(wd[0], wv.x); PACK_DUP(wd[1], wv.y);
            PACK_DUP(wd[2], wv.z); PACK_DUP(wd[3], wv.w);
#pragma unroll
            for (int i = 0; i < MP; i++)
#pragma unroll
                for (int j = 0; j < 4; j++)
                    FMA2(acc[i][j], ap[i], wd[j]);
        }
        __syncthreads();
    }

    // ---- epilogue ----
    const int coff = colOffPerZ * z;
#pragma unroll
    for (int i = 0; i < MP; i++) {
        int mA = m0 + ty * MT + 2 * i;
        int mB = mA + 1;
        int rA = mA, rB = mB;
        if ((flags & FLAG_FLIP) && z == 1) {
            rA = (mA & ~(SS - 1)) + ((SS - 1) - (mA & (SS - 1)));
            rB = (mB & ~(SS - 1)) + ((SS - 1) - (mB & (SS - 1)));
        }
        float* crowA = C + (size_t)z * sCz + (size_t)rA * ldc + coff;
        float* crowB = C + (size_t)z * sCz + (size_t)rB * ldc + coff;
#pragma unroll
        for (int j = 0; j < 4; j++) {
            int n = n0 + tx * 4 + j;
            if (n < N_) {
                float vA, vB;
                UNPACK2(vA, vB, acc[i][j]);
                if (bias) {
                    float bv = bias[z * sBiasZ + n];
                    vA += bv; vB += bv;
                }
                if (flags & FLAG_SOFTPLUS) {
                    vA = (vA > 20.f) ? vA : log1pf(__expf(vA));
                    vB = (vB > 20.f) ? vB : log1pf(__expf(vB));
                }
                if (resid) {
                    vA += resid[(size_t)rA * ldc + coff + n];
                    vB += resid[(size_t)rB * ldc + coff + n];
                }
                crowA[n] = vA;
                crowB[n] = vB;
            }
        }
    }
}

// ---------------- LayerNorm (optionally slice cols + flip S for z==1) ----------------
__device__ __forceinline__ void block_reduce_2(float& s1, float& s2)
{
    __shared__ float sh1[8], sh2[8];
#pragma unroll
    for (int o = 16; o > 0; o >>= 1) {
        s1 += __shfl_xor_sync(0xffffffffu, s1, o);
        s2 += __shfl_xor_sync(0xffffffffu, s2, o);
    }
    int lane = threadIdx.x & 31, wid = threadIdx.x >> 5;
    if (lane == 0) { sh1[wid] = s1; sh2[wid] = s2; }
    __syncthreads();
    if (threadIdx.x == 0) {
        float a = 0.f, b = 0.f;
#pragma unroll
        for (int i = 0; i < 8; i++) { a += sh1[i]; b += sh2[i]; }
        sh1[0] = a; sh2[0] = b;
    }
    __syncthreads();
    s1 = sh1[0]; s2 = sh2[0];
}

__global__ __launch_bounds__(256) void ln_kernel(
    const float* __restrict__ src, int ldsrc, int colOffPerZ, int flipz,
    const float* __restrict__ g, const float* __restrict__ bta, int gbStrideZ,
    float* __restrict__ dst, int lddst, long long dstStrideZ, int Dvec)
{
    const int m = blockIdx.x, z = blockIdx.y;
    int srow = m;
    if (flipz && z == 1)
        srow = (m & ~(SS - 1)) + ((SS - 1) - (m & (SS - 1)));
    const float* sp = src + (size_t)srow * ldsrc + colOffPerZ * z;
    const int tid = threadIdx.x;

    float v0 = sp[tid];
    float v1 = (Dvec > 256) ? sp[tid + 256] : 0.f;
    float s1 = v0 + v1, s2 = v0 * v0 + v1 * v1;
    block_reduce_2(s1, s2);

    const float invD = 1.f / (float)Dvec;
    float mean = s1 * invD;
    float var  = s2 * invD - mean * mean;
    float inv  = rsqrtf(var + 1e-5f);

    const float* gz = g + z * gbStrideZ;
    const float* bz = bta + z * gbStrideZ;
    float* dp = dst + (size_t)z * dstStrideZ + (size_t)m * lddst;
    dp[tid] = (v0 - mean) * inv * gz[tid] + bz[tid];
    if (Dvec > 256)
        dp[tid + 256] = (v1 - mean) * inv * gz[tid + 256] + bz[tid + 256];
}

// ---------------- causal depthwise conv (K=4) + SiLU, float4-vectorized ----------------
__global__ __launch_bounds__(256) void conv_silu_kernel(
    const float* __restrict__ xz,   // [2][MM][1024], cols 0..511 are xc-raw
    const float* __restrict__ cW,   // [2][512][4]
    const float* __restrict__ cB,   // [2][512]
    float* __restrict__ xc)         // [2][MM][512]
{
    int idx = blockIdx.x * 256 + threadIdx.x;      // < 2*MM*128
    int d4  = (idx & 127) << 2;                    // 0,4,..508
    int row = (idx >> 7) & (MM - 1);
    int z   = idx >> 18;
    int s   = row & (SS - 1);
    int bs0 = row - s;

    // weights for 4 consecutive channels: cW rows d4..d4+3, each 4 floats
    float4 w0 = *reinterpret_cast<const float4*>(&cW[((size_t)z * 512 + d4 + 0) * 4]);
    float4 w1 = *reinterpret_cast<const float4*>(&cW[((size_t)z * 512 + d4 + 1) * 4]);
    float4 w2 = *reinterpret_cast<const float4*>(&cW[((size_t)z * 512 + d4 + 2) * 4]);
    float4 w3 = *reinterpret_cast<const float4*>(&cW[((size_t)z * 512 + d4 + 3) * 4]);
    float4 b  = *reinterpret_cast<const float4*>(&cB[z * 512 + d4]);

    float4 accv = b;
    const float* xzz = xz + (size_t)z * MM * 1024;
#pragma unroll
    for (int k = 0; k < 4; k++) {
        int sp = s - 3 + k;
        if (sp >= 0) {
            float4 xv = *reinterpret_cast<const float4*>(
                &xzz[(size_t)(bs0 + sp) * 1024 + d4]);
            float wk0 = (&w0.x)[k], wk1 = (&w1.x)[k], wk2 = (&w2.x)[k], wk3 = (&w3.x)[k];
            accv.x = fmaf(wk0, xv.x, accv.x);
            accv.y = fmaf(wk1, xv.y, accv.y);
            accv.z = fmaf(wk2, xv.z, accv.z);
            accv.w = fmaf(wk3, xv.w, accv.w);
        }
    }
    accv.x *= 1.f / (1.f + __expf(-accv.x));
    accv.y *= 1.f / (1.f + __expf(-accv.y));
    accv.z *= 1.f / (1.f + __expf(-accv.z));
    accv.w *= 1.f / (1.f + __expf(-accv.w));
    *reinterpret_cast<float4*>(
        &xc[(size_t)z * MM * 512 + (size_t)row * 512 + d4]) = accv;
}

// ---------------- chunked SSM scan ----------------
// Phase 1: per (z,b,chunk,d): P[n] = prod exp(dt*A[n]); hend[n] = chunk scan from h=0.
__global__ __launch_bounds__(256) void scan_phase1(
    const float* __restrict__ dtp,   // [2][MM][512]
    const float* __restrict__ xcp,   // [2][MM][512]
    const float* __restrict__ dblp,  // [2][MM][48] (B at 16..31)
    const float* __restrict__ A_log_l, // [2][512][16]
    float* __restrict__ P, float* __restrict__ hend)
{
    const int chunk = blockIdx.x >> 1;
    const int dg    = blockIdx.x & 1;
    const int b     = blockIdx.y, z = blockIdx.z;
    const int d     = dg * 256 + threadIdx.x;

    __shared__ float sB[TCH][NST];
    const float* dbl_z = dblp + (size_t)z * MM * 48;
    const int base = b * SS + chunk * TCH;
    for (int i = threadIdx.x; i < TCH * NST; i += 256) {
        int t = i >> 4, n = i & 15;
        sB[t][n] = dbl_z[(size_t)(base + t) * 48 + 16 + n];
    }
    __syncthreads();

    float a[NST];
    const float* al = A_log_l + ((size_t)z * 512 + d) * NST;
#pragma unroll
    for (int n = 0; n < NST; n++) a[n] = -expf(al[n]);

    float h[NST], Pr[NST];
#pragma unroll
    for (int n = 0; n < NST; n++) { h[n] = 0.f; Pr[n] = 1.f; }

    const float* dtz = dtp + (size_t)z * MM * 512;
    const float* xcz = xcp + (size_t)z * MM * 512;
    for (int t = 0; t < TCH; t++) {
        int row = base + t;
        float dtv = dtz[(size_t)row * 512 + d];
        float xv  = xcz[(size_t)row * 512 + d];
        float dx  = dtv * xv;
#pragma unroll
        for (int n = 0; n < NST; n++) {
            float dA = __expf(dtv * a[n]);
            h[n]  = fmaf(dA, h[n], dx * sB[t][n]);
            Pr[n] *= dA;
        }
    }
    size_t ob = ((((size_t)z * 2 + b) * NCH + chunk) * NST) * 512 + d;
#pragma unroll
    for (int n = 0; n < NST; n++) {
        P[ob + (size_t)n * 512]    = Pr[n];
        hend[ob + (size_t)n * 512] = h[n];
    }
}

// Phase 2: stitch across 32 chunks, parallel over (z,b,n,d) = 32768 threads.
// All loads hoisted to registers (full MLP), then a pure-FMA chain.
__global__ __launch_bounds__(256) void scan_phase2(
    const float* __restrict__ P, const float* __restrict__ hend,
    float* __restrict__ hinit)
{
    int idx = blockIdx.x * 256 + threadIdx.x;   // 0..32767
    int d = idx & 511;
    int n = (idx >> 9) & 15;
    int b = (idx >> 13) & 1;
    int z = idx >> 14;
    size_t base = ((((size_t)z * 2 + b) * NCH) * NST + n) * 512 + d;
    const size_t cs = (size_t)NST * 512;

    float Pv[NCH], He[NCH];
#pragma unroll
    for (int c = 0; c < NCH; c++) {
        Pv[c] = P[base + (size_t)c * cs];
        He[c] = hend[base + (size_t)c * cs];
    }
    float h = 0.f;
#pragma unroll
    for (int c = 0; c < NCH; c++) {
        hinit[base + (size_t)c * cs] = h;
        h = fmaf(Pv[c], h, He[c]);
    }
}

// Phase 3: replay with correct init; y = (scan + xc*Dp) * silu(z-gate)
__global__ __launch_bounds__(256) void scan_phase3(
    const float* __restrict__ dtp, const float* __restrict__ xcp,
    const float* __restrict__ dblp, const float* __restrict__ A_log_l,
    const float* __restrict__ hinit,
    const float* __restrict__ xzp,  // [2][MM][1024], z-gate at cols 512..1023
    const float* __restrict__ Dp_l, // [2][512]
    float* __restrict__ yg)         // [2][MM][512]
{
    const int chunk = blockIdx.x >> 1;
    const int dg    = blockIdx.x & 1;
    const int b     = blockIdx.y, z = blockIdx.z;
    const int d     = dg * 256 + threadIdx.x;

    __shared__ float sBC[TCH][32];   // B at [t][0..15], C at [t][16..31]
    const float* dbl_z = dblp + (size_t)z * MM * 48;
    const int base = b * SS + chunk * TCH;
    for (int i = threadIdx.x; i < TCH * 32; i += 256) {
        int t = i >> 5, n = i & 31;
        sBC[t][n] = dbl_z[(size_t)(base + t) * 48 + 16 + n];
    }
    __syncthreads();

    float a[NST];
    const float* al = A_log_l + ((size_t)z * 512 + d) * NST;
#pragma unroll
    for (int n = 0; n < NST; n++) a[n] = -expf(al[n]);

    float h[NST];
    {
        size_t ob = ((((size_t)z * 2 + b) * NCH + chunk) * NST) * 512 + d;
#pragma unroll
        for (int n = 0; n < NST; n++) h[n] = hinit[ob + (size_t)n * 512];
    }
    const float Dv = Dp_l[z * 512 + d];
    const float* dtz = dtp + (size_t)z * MM * 512;
    const float* xcz = xcp + (size_t)z * MM * 512;
    const float* xzz = xzp + (size_t)z * MM * 1024;
    float* ygz = yg + (size_t)z * MM * 512;

    for (int t = 0; t < TCH; t++) {
        int row = base + t;
        float dtv = dtz[(size_t)row * 512 + d];
        float xv  = xcz[(size_t)row * 512 + d];
        float dx  = dtv * xv;
        float y = 0.f;
#pragma unroll
        for (int n = 0; n < NST; n++) {
            float dA = __expf(dtv * a[n]);
            h[n] = fmaf(dA, h[n], dx * sBC[t][n]);
            y = fmaf(h[n], sBC[t][16 + n], y);
        }
        float yfull = fmaf(xv, Dv, y);
        float zv = xzz[(size_t)row * 1024 + 512 + d];
        float sig = 1.f / (1.f + __expf(-zv));
        ygz[(size_t)row * 512 + d] = yfull * zv * sig;
    }
}

// ---------------- host orchestration ----------------
extern "C" void kernel_launch(void* const* d_in, const int* in_sizes, int n_in,
                              void* d_out, int out_size)
{
    const float* x      = (const float*)d_in[0];
    const float* ln_g   = (const float*)d_in[1];
    const float* ln_b   = (const float*)d_in[2];
    const float* inW    = (const float*)d_in[3];
    const float* convW  = (const float*)d_in[4];
    const float* convB  = (const float*)d_in[5];
    const float* xprojW = (const float*)d_in[6];
    const float* dtW    = (const float*)d_in[7];
    const float* dtB    = (const float*)d_in[8];
    const float* A_log  = (const float*)d_in[9];
    const float* Dp     = (const float*)d_in[10];
    const float* outW   = (const float*)d_in[11];
    const float* ipW    = (const float*)d_in[12];
    const float* ipB    = (const float*)d_in[13];
    const float* opW    = (const float*)d_in[14];
    const float* opB    = (const float*)d_in[15];
    const float* fln_g  = (const float*)d_in[16];
    const float* fln_b  = (const float*)d_in[17];

    float* scratch = nullptr;
    cudaGetSymbolAddress((void**)&scratch, g_scratch);
    float* xp   = scratch + OFF_XP;
    float* xn   = scratch + OFF_XN;
    float* xzb  = scratch + OFF_XZ;
    float* xc   = scratch + OFF_XC;
    float* dbl  = scratch + OFF_DBL;
    float* dtb  = scratch + OFF_DT;
    float* yg   = scratch + OFF_YG;
    float* ycat = scratch + OFF_YCAT;
    float* hbuf[2] = { scratch + OFF_H0, scratch + OFF_H1 };
    float* Pb   = scratch + OFF_P;
    float* heb  = scratch + OFF_HEND;
    float* hib  = scratch + OFF_HINIT;

    const float* hin = x;
    for (int l = 0; l < LNUM; l++) {
        const size_t l2 = (size_t)l * 2;

        // xp = hin @ ipW_l^T + ipB_l              (M=2048, N=512, K=512)
        gemm2_kernel<128><<<dim3(8, 16, 1), 256>>>(
            hin, 512, 0, ipW + (size_t)l * 512 * 512, 512, 0,
            xp, 512, 0, 0, ipB + l * 512, 0, nullptr, 512, 512, 0);

        // per-dir LN over 256 (dir1 reads cols 256.. with flipped S)
        ln_kernel<<<dim3(MM, 2), 256>>>(
            xp, 512, 256, 1, ln_g + l2 * 256, ln_b + l2 * 256, 256,
            xn, 256, (long long)MM * 256, 256);

        // xz = xn @ inW^T                          (N=1024, K=256), both dirs
        gemm2_kernel<128><<<dim3(16, 16, 2), 256>>>(
            xn, 256, (long long)MM * 256,
            inW + l2 * 1024 * 256, 256, (long long)1024 * 256,
            xzb, 1024, (long long)MM * 1024, 0, nullptr, 0, nullptr, 1024, 256, 0);

        // causal dwconv + silu on xz[..,:512]
        conv_silu_kernel<<<(2 * MM * 128) / 256, 256>>>(
            xzb, convW + l2 * 512 * 4, convB + l2 * 512, xc);

        // dbl = xc @ xprojW^T                      (N=48, K=512), BM=64 for occupancy
        gemm2_kernel<64><<<dim3(1, 32, 2), 256>>>(
            xc, 512, (long long)MM * 512,
            xprojW + l2 * 48 * 512, 512, (long long)48 * 512,
            dbl, 48, (long long)MM * 48, 0, nullptr, 0, nullptr, 48, 512, 0);

        // dt = softplus(dbl[:,:16] @ dtW^T + dtB)  (N=512, K=16)
        gemm2_kernel<128><<<dim3(8, 16, 2), 256>>>(
            dbl, 48, (long long)MM * 48,
            dtW + l2 * 512 * 16, 16, (long long)512 * 16,
            dtb, 512, (long long)MM * 512, 0,
            dtB + l2 * 512, 512, nullptr, 512, 16, FLAG_SOFTPLUS);

        // chunked scan
        scan_phase1<<<dim3(NCH * 2, 2, 2), 256>>>(
            dtb, xc, dbl, A_log + l2 * 512 * NST, Pb, heb);
        scan_phase2<<<128, 256>>>(Pb, heb, hib);
        scan_phase3<<<dim3(NCH * 2, 2, 2), 256>>>(
            dtb, xc, dbl, A_log + l2 * 512 * NST, hib, xzb, Dp + l2 * 512, yg);

        // per-dir out: ycat[:, z*256..] = u + yg @ outW^T   (N=256, K=512), dir1 flip-store
        gemm2_kernel<128><<<dim3(4, 16, 2), 256>>>(
            yg, 512, (long long)MM * 512,
            outW + l2 * 256 * 512, 512, (long long)256 * 512,
            ycat, 512, 0, 256, nullptr, 0, xp, 256, 512, FLAG_FLIP);

        // h_next = ycat @ opW^T + opB              (N=512, K=512)
        float* hout = hbuf[l & 1];
        gemm2_kernel<128><<<dim3(8, 16, 1), 256>>>(
            ycat, 512, 0, opW + (size_t)l * 512 * 512, 512, 0,
            hout, 512, 0, 0, opB + l * 512, 0, nullptr, 512, 512, 0);
        hin = hout;
    }

    // final LN over 512 -> d_out
    ln_kernel<<<dim3(MM, 1), 256>>>(
        hin, 512, 0, 0, fln_g, fln_b, 0,
        (float*)d_out, 512, 0, 512);
}

// round 5
// speedup vs baseline: 1.6954x; 1.3005x over previous
#include <cuda_runtime.h>
#include <cuda_bf16.h>
#include <cstdint>

// Problem constants
#define LNUM 2
#define SS   1024
#define MM   2048      // B*S tokens
#define NST  16        // SSM state dim
#define NCH  32        // scan chunks
#define TCH  32        // steps per chunk

#define FLAG_SOFTPLUS 1
#define FLAG_FLIP     2

// ---------------- scratch (static device memory; no allocation) ----------------
#define OFF_XP    0
#define OFF_XN    (OFF_XP   + MM*512)
#define OFF_XZ    (OFF_XN   + 2*MM*256)
#define OFF_XC    (OFF_XZ   + 2*MM*1024)
#define OFF_DBL   (OFF_XC   + 2*MM*512)
#define OFF_DT    (OFF_DBL  + 2*MM*48)
#define OFF_YG    (OFF_DT   + 2*MM*512)
#define OFF_YCAT  (OFF_YG   + 2*MM*512)
#define OFF_H0    (OFF_YCAT + MM*512)
#define OFF_H1    (OFF_H0   + MM*512)
#define OFF_P     (OFF_H1   + MM*512)
#define OFF_HEND  (OFF_P    + 2*2*NCH*NST*512)
#define OFF_HINIT (OFF_HEND + 2*2*NCH*NST*512)
#define SCRATCH_TOTAL (OFF_HINIT + 2*2*NCH*NST*512)

__device__ float g_scratch[SCRATCH_TOTAL];

__device__ __forceinline__ uint32_t cvt_tf32(float f) {
    uint32_t r; asm("cvt.rna.tf32.f32 %0, %1;" : "=r"(r) : "f"(f)); return r;
}

__device__ __forceinline__ void mma_tf32(float4& c, const uint32_t a[4], const uint32_t b[2]) {
    asm volatile(
        "mma.sync.aligned.m16n8k8.row.col.f32.tf32.tf32.f32 "
        "{%0,%1,%2,%3}, {%4,%5,%6,%7}, {%8,%9}, {%0,%1,%2,%3};"
        : "+f"(c.x), "+f"(c.y), "+f"(c.z), "+f"(c.w)
        : "r"(a[0]), "r"(a[1]), "r"(a[2]), "r"(a[3]), "r"(b[0]), "r"(b[1]));
}

// ================= tf32 mma.sync GEMM =================
// C = A(M x K) @ W(N x K)^T (+bias)(+resid, flip-store).
// Block 128x128, BK=16, 256 threads (8 warps, 2m x 4n), warp tile 64x32.
// N must be a multiple of 128; K a multiple of 16.
__global__ __launch_bounds__(256) void gemm_mma_kernel(
    const float* __restrict__ A, int lda, long long sAz,
    const float* __restrict__ W, int ldw, long long sWz,
    float* __restrict__ C, int ldc, long long sCz, int colOffPerZ,
    const float* __restrict__ bias, int sBiasZ,
    const float* __restrict__ resid,
    int K_, int flags)
{
    __shared__ __align__(16) float As[128][20];   // [m][k], stride 20 -> conflict-free frags
    __shared__ __align__(16) float Ws[16][136];   // [k][n], stride 136 -> conflict-free frags

    const int tid = threadIdx.x;
    const int wid = tid >> 5, lane = tid & 31;
    const int wm = wid >> 2, wn = wid & 3;        // warp grid 2 x 4
    const int r = lane >> 2, c = lane & 3;

    const int z = blockIdx.z;
    const int m0 = blockIdx.y * 128, n0 = blockIdx.x * 128;
    const float* Ab = A + (size_t)z * sAz;
    const float* Wb = W + (size_t)z * sWz;

    float4 acc[4][4];
#pragma unroll
    for (int i = 0; i < 4; i++)
#pragma unroll
        for (int j = 0; j < 4; j++) acc[i][j] = make_float4(0.f, 0.f, 0.f, 0.f);

    // register staging for prefetch: 2 float4 each for A and W
    float4 ar[2], wr[2];
#pragma unroll
    for (int i = 0; i < 2; i++) {
        int f = tid + i * 256;
        int row = f >> 2, kq = (f & 3) << 2;
        ar[i] = *reinterpret_cast<const float4*>(&Ab[(size_t)(m0 + row) * lda + kq]);
        wr[i] = *reinterpret_cast<const float4*>(&Wb[(size_t)(n0 + row) * ldw + kq]);
    }

    for (int k0 = 0; k0 < K_; k0 += 16) {
        // ---- store staged chunk to smem (tf32-rounded) ----
#pragma unroll
        for (int i = 0; i < 2; i++) {
            int f = tid + i * 256;
            int row = f >> 2, kq = (f & 3) << 2;
            float4 av = ar[i];
            av.x = __uint_as_float(cvt_tf32(av.x));
            av.y = __uint_as_float(cvt_tf32(av.y));
            av.z = __uint_as_float(cvt_tf32(av.z));
            av.w = __uint_as_float(cvt_tf32(av.w));
            *reinterpret_cast<float4*>(&As[row][kq]) = av;
            float4 wv = wr[i];
            Ws[kq + 0][row] = __uint_as_float(cvt_tf32(wv.x));
            Ws[kq + 1][row] = __uint_as_float(cvt_tf32(wv.y));
            Ws[kq + 2][row] = __uint_as_float(cvt_tf32(wv.z));
            Ws[kq + 3][row] = __uint_as_float(cvt_tf32(wv.w));
        }
        __syncthreads();

        // ---- prefetch next chunk ----
        if (k0 + 16 < K_) {
#pragma unroll
            for (int i = 0; i < 2; i++) {
                int f = tid + i * 256;
                int row = f >> 2, kq = (f & 3) << 2;
                ar[i] = *reinterpret_cast<const float4*>(
                    &Ab[(size_t)(m0 + row) * lda + k0 + 16 + kq]);
                wr[i] = *reinterpret_cast<const float4*>(
                    &Wb[(size_t)(n0 + row) * ldw + k0 + 16 + kq]);
            }
        }

        // ---- compute: 2 k-steps of m16n8k8 ----
#pragma unroll
        for (int kk = 0; kk < 2; kk++) {
            const int kb = kk * 8;
            uint32_t af[4][2][4];   // reuse as af[mt][..]; layout below
            uint32_t bf[4][2];
            uint32_t afr[4][4];
#pragma unroll
            for (int mt = 0; mt < 4; mt++) {
                int m = wm * 64 + mt * 16 + r;
                afr[mt][0] = __float_as_uint(As[m][kb + c]);
                afr[mt][1] = __float_as_uint(As[m + 8][kb + c]);
                afr[mt][2] = __float_as_uint(As[m][kb + c + 4]);
                afr[mt][3] = __float_as_uint(As[m + 8][kb + c + 4]);
            }
#pragma unroll
            for (int nt = 0; nt < 4; nt++) {
                int n = wn * 32 + nt * 8 + r;
                bf[nt][0] = __float_as_uint(Ws[kb + c][n]);
                bf[nt][1] = __float_as_uint(Ws[kb + c + 4][n]);
            }
            (void)af;
#pragma unroll
            for (int mt = 0; mt < 4; mt++)
#pragma unroll
                for (int nt = 0; nt < 4; nt++)
                    mma_tf32(acc[mt][nt], afr[mt], bf[nt]);
        }
        __syncthreads();
    }

    // ---- epilogue ----
    const int coff = colOffPerZ * z;
#pragma unroll
    for (int mt = 0; mt < 4; mt++) {
        int mA = m0 + wm * 64 + mt * 16 + r;
        int mB = mA + 8;
        int rA = mA, rB = mB;
        if ((flags & FLAG_FLIP) && z == 1) {
            rA = (mA & ~(SS - 1)) + ((SS - 1) - (mA & (SS - 1)));
            rB = (mB & ~(SS - 1)) + ((SS - 1) - (mB & (SS - 1)));
        }
        float* rowA = C + (size_t)z * sCz + (size_t)rA * ldc + coff;
        float* rowB = C + (size_t)z * sCz + (size_t)rB * ldc + coff;
        const float* resA = resid ? (resid + (size_t)rA * ldc + coff) : nullptr;
        const float* resB = resid ? (resid + (size_t)rB * ldc + coff) : nullptr;
#pragma unroll
        for (int nt = 0; nt < 4; nt++) {
            int n = n0 + wn * 32 + nt * 8 + 2 * c;
            float2 vA = make_float2(acc[mt][nt].x, acc[mt][nt].y);
            float2 vB = make_float2(acc[mt][nt].z, acc[mt][nt].w);
            if (bias) {
                float2 bv = *reinterpret_cast<const float2*>(&bias[z * sBiasZ + n]);
                vA.x += bv.x; vA.y += bv.y;
                vB.x += bv.x; vB.y += bv.y;
            }
            if (flags & FLAG_SOFTPLUS) {
                vA.x = (vA.x > 20.f) ? vA.x : log1pf(__expf(vA.x));
                vA.y = (vA.y > 20.f) ? vA.y : log1pf(__expf(vA.y));
                vB.x = (vB.x > 20.f) ? vB.x : log1pf(__expf(vB.x));
                vB.y = (vB.y > 20.f) ? vB.y : log1pf(__expf(vB.y));
            }
            if (resA) {
                float2 qa = *reinterpret_cast<const float2*>(&resA[n]);
                float2 qb = *reinterpret_cast<const float2*>(&resB[n]);
                vA.x += qa.x; vA.y += qa.y;
                vB.x += qb.x; vB.y += qb.y;
            }
            *reinterpret_cast<float2*>(&rowA[n]) = vA;
            *reinterpret_cast<float2*>(&rowB[n]) = vB;
        }
    }
}

// ================= f32x2 fp32 GEMM (small shapes: xproj N=48, dt K=16) =================
#define PACK_DUP(dst, s) asm("mov.b64 %0, {%1, %1};" : "=l"(dst) : "f"(s))
#define FMA2(acc, a, b)  asm("fma.rn.f32x2 %0, %1, %2, %0;" : "+l"(acc) : "l"(a), "l"(b))
#define UNPACK2(lo, hi, v) asm("mov.b64 {%0, %1}, %2;" : "=f"(lo), "=f"(hi) : "l"(v))

template<int BMT>
__global__ __launch_bounds__(256, 2) void gemm2_kernel(
    const float* __restrict__ A, int lda, long long sAz,
    const float* __restrict__ W, int ldw, long long sWz,
    float* __restrict__ C, int ldc, long long sCz, int colOffPerZ,
    const float* __restrict__ bias, int sBiasZ,
    const float* __restrict__ resid,
    int N_, int K_, int flags)
{
    constexpr int MT = BMT / 16;
    constexpr int MP = MT / 2;
    constexpr int AL = BMT + 4;
    constexpr int NA = BMT / 64;

    const int z  = blockIdx.z;
    const float* Ab = A + (size_t)z * sAz;
    const float* Wb = W + (size_t)z * sWz;
    const int m0 = blockIdx.y * BMT;
    const int n0 = blockIdx.x * 64;

    __shared__ __align__(16) float As[16][AL];
    __shared__ __align__(16) float Ws[16][68];

    unsigned long long acc[MP][4];
#pragma unroll
    for (int i = 0; i < MP; i++)
#pragma unroll
        for (int j = 0; j < 4; j++) acc[i][j] = 0ULL;

    const int tid = threadIdx.x;
    const int tx = tid & 15, ty = tid >> 4;

    float4 aFrag[NA];
    float4 wFrag;
    {
#pragma unroll
        for (int i = 0; i < NA; i++) {
            int lin = tid + i * 256;
            int m = lin >> 2, kq = (lin & 3) << 2;
            aFrag[i] = *reinterpret_cast<const float4*>(
                &Ab[(size_t)(m0 + m) * lda + kq]);
        }
        int n = tid >> 2, kq = (tid & 3) << 2;
        wFrag = make_float4(0.f, 0.f, 0.f, 0.f);
        if (n0 + n < N_)
            wFrag = *reinterpret_cast<const float4*>(
                &Wb[(size_t)(n0 + n) * ldw + kq]);
    }

    for (int k0 = 0; k0 < K_; k0 += 16) {
#pragma unroll
        for (int i = 0; i < NA; i++) {
            int lin = tid + i * 256;
            int m = lin >> 2, kq = (lin & 3) << 2;
            As[kq + 0][m] = aFrag[i].x; As[kq + 1][m] = aFrag[i].y;
            As[kq + 2][m] = aFrag[i].z; As[kq + 3][m] = aFrag[i].w;
        }
        {
            int n = tid >> 2, kq = (tid & 3) << 2;
            Ws[kq + 0][n] = wFrag.x; Ws[kq + 1][n] = wFrag.y;
            Ws[kq + 2][n] = wFrag.z; Ws[kq + 3][n] = wFrag.w;
        }
        __syncthreads();

        if (k0 + 16 < K_) {
#pragma unroll
            for (int i = 0; i < NA; i++) {
                int lin = tid + i * 256;
                int m = lin >> 2, kq = (lin & 3) << 2;
                aFrag[i] = *reinterpret_cast<const float4*>(
                    &Ab[(size_t)(m0 + m) * lda + k0 + 16 + kq]);
            }
            int n = tid >> 2, kq = (tid & 3) << 2;
            wFrag = make_float4(0.f, 0.f, 0.f, 0.f);
            if (n0 + n < N_)
                wFrag = *reinterpret_cast<const float4*>(
                    &Wb[(size_t)(n0 + n) * ldw + k0 + 16 + kq]);
        }

#pragma unroll
        for (int k = 0; k < 16; k++) {
            unsigned long long ap[MP];
            {
                ulonglong2 q0 = *reinterpret_cast<const ulonglong2*>(&As[k][ty * MT]);
                ap[0] = q0.x; ap[1] = q0.y;
                if (MP == 4) {
                    ulonglong2 q1 = *reinterpret_cast<const ulonglong2*>(&As[k][ty * MT + 4]);
                    ap[2] = q1.x; ap[3] = q1.y;
                }
            }
            float4 wv = *reinterpret_cast<const float4*>(&Ws[k][tx * 4]);
            unsigned long long wd[4];
            PACK_DUP(wd[0], wv.x); PACK_DUP(wd[1], wv.y);
            PACK_DUP(wd[2], wv.z); PACK_DUP(wd[3], wv.w);
#pragma unroll
            for (int i = 0; i < MP; i++)
#pragma unroll
                for (int j = 0; j < 4; j++)
                    FMA2(acc[i][j], ap[i], wd[j]);
        }
        __syncthreads();
    }

    const int coff = colOffPerZ * z;
#pragma unroll
    for (int i = 0; i < MP; i++) {
        int mA = m0 + ty * MT + 2 * i;
        int mB = mA + 1;
        int rA = mA, rB = mB;
        if ((flags & FLAG_FLIP) && z == 1) {
            rA = (mA & ~(SS - 1)) + ((SS - 1) - (mA & (SS - 1)));
            rB = (mB & ~(SS - 1)) + ((SS - 1) - (mB & (SS - 1)));
        }
        float* crowA = C + (size_t)z * sCz + (size_t)rA * ldc + coff;
        float* crowB = C + (size_t)z * sCz + (size_t)rB * ldc + coff;
#pragma unroll
        for (int j = 0; j < 4; j++) {
            int n = n0 + tx * 4 + j;
            if (n < N_) {
                float vA, vB;
                UNPACK2(vA, vB, acc[i][j]);
                if (bias) {
                    float bv = bias[z * sBiasZ + n];
                    vA += bv; vB += bv;
                }
                if (flags & FLAG_SOFTPLUS) {
                    vA = (vA > 20.f) ? vA : log1pf(__expf(vA));
                    vB = (vB > 20.f) ? vB : log1pf(__expf(vB));
                }
                if (resid) {
                    vA += resid[(size_t)rA * ldc + coff + n];
                    vB += resid[(size_t)rB * ldc + coff + n];
                }
                crowA[n] = vA;
                crowB[n] = vB;
            }
        }
    }
}

// ---------------- LayerNorm ----------------
__device__ __forceinline__ void block_reduce_2(float& s1, float& s2)
{
    __shared__ float sh1[8], sh2[8];
#pragma unroll
    for (int o = 16; o > 0; o >>= 1) {
        s1 += __shfl_xor_sync(0xffffffffu, s1, o);
        s2 += __shfl_xor_sync(0xffffffffu, s2, o);
    }
    int lane = threadIdx.x & 31, wid = threadIdx.x >> 5;
    if (lane == 0) { sh1[wid] = s1; sh2[wid] = s2; }
    __syncthreads();
    if (threadIdx.x == 0) {
        float a = 0.f, b = 0.f;
#pragma unroll
        for (int i = 0; i < 8; i++) { a += sh1[i]; b += sh2[i]; }
        sh1[0] = a; sh2[0] = b;
    }
    __syncthreads();
    s1 = sh1[0]; s2 = sh2[0];
}

__global__ __launch_bounds__(256) void ln_kernel(
    const float* __restrict__ src, int ldsrc, int colOffPerZ, int flipz,
    const float* __restrict__ g, const float* __restrict__ bta, int gbStrideZ,
    float* __restrict__ dst, int lddst, long long dstStrideZ, int Dvec)
{
    const int m = blockIdx.x, z = blockIdx.y;
    int srow = m;
    if (flipz && z == 1)
        srow = (m & ~(SS - 1)) + ((SS - 1) - (m & (SS - 1)));
    const float* sp = src + (size_t)srow * ldsrc + colOffPerZ * z;
    const int tid = threadIdx.x;

    float v0 = sp[tid];
    float v1 = (Dvec > 256) ? sp[tid + 256] : 0.f;
    float s1 = v0 + v1, s2 = v0 * v0 + v1 * v1;
    block_reduce_2(s1, s2);

    const float invD = 1.f / (float)Dvec;
    float mean = s1 * invD;
    float var  = s2 * invD - mean * mean;
    float inv  = rsqrtf(var + 1e-5f);

    const float* gz = g + z * gbStrideZ;
    const float* bz = bta + z * gbStrideZ;
    float* dp = dst + (size_t)z * dstStrideZ + (size_t)m * lddst;
    dp[tid] = (v0 - mean) * inv * gz[tid] + bz[tid];
    if (Dvec > 256)
        dp[tid + 256] = (v1 - mean) * inv * gz[tid + 256] + bz[tid + 256];
}

// ---------------- causal depthwise conv (K=4) + SiLU ----------------
__global__ __launch_bounds__(256) void conv_silu_kernel(
    const float* __restrict__ xz,   // [2][MM][1024], cols 0..511 are xc-raw
    const float* __restrict__ cW,   // [2][512][4]
    const float* __restrict__ cB,   // [2][512]
    float* __restrict__ xc)         // [2][MM][512]
{
    int idx = blockIdx.x * 256 + threadIdx.x;      // < 2*MM*512 = 2^21
    int d   = idx & 511;
    int row = (idx >> 9) & (MM - 1);
    int z   = idx >> 20;
    int s   = row & (SS - 1);
    int bs0 = row - s;

    const float4 wv = *reinterpret_cast<const float4*>(&cW[((size_t)z * 512 + d) * 4]);
    const float w[4] = {wv.x, wv.y, wv.z, wv.w};
    float acc = cB[z * 512 + d];
    const float* xzz = xz + (size_t)z * MM * 1024;
#pragma unroll
    for (int k = 0; k < 4; k++) {
        int sp = s - 3 + k;
        if (sp >= 0) acc += w[k] * xzz[(size_t)(bs0 + sp) * 1024 + d];
    }
    float sig = 1.f / (1.f + __expf(-acc));
    xc[(size_t)z * MM * 512 + (size_t)row * 512 + d] = acc * sig;
}

// ---------------- chunked SSM scan ----------------
__global__ __launch_bounds__(256) void scan_phase1(
    const float* __restrict__ dtp, const float* __restrict__ xcp,
    const float* __restrict__ dblp, const float* __restrict__ A_log_l,
    float* __restrict__ P, float* __restrict__ hend)
{
    const int chunk = blockIdx.x >> 1;
    const int dg    = blockIdx.x & 1;
    const int b     = blockIdx.y, z = blockIdx.z;
    const int d     = dg * 256 + threadIdx.x;

    __shared__ float sB[TCH][NST];
    const float* dbl_z = dblp + (size_t)z * MM * 48;
    const int base = b * SS + chunk * TCH;
    for (int i = threadIdx.x; i < TCH * NST; i += 256) {
        int t = i >> 4, n = i & 15;
        sB[t][n] = dbl_z[(size_t)(base + t) * 48 + 16 + n];
    }
    __syncthreads();

    float a[NST];
    const float* al = A_log_l + ((size_t)z * 512 + d) * NST;
#pragma unroll
    for (int n = 0; n < NST; n++) a[n] = -expf(al[n]);

    float h[NST], Pr[NST];
#pragma unroll
    for (int n = 0; n < NST; n++) { h[n] = 0.f; Pr[n] = 1.f; }

    const float* dtz = dtp + (size_t)z * MM * 512;
    const float* xcz = xcp + (size_t)z * MM * 512;
    for (int t = 0; t < TCH; t++) {
        int row = base + t;
        float dtv = dtz[(size_t)row * 512 + d];
        float xv  = xcz[(size_t)row * 512 + d];
        float dx  = dtv * xv;
#pragma unroll
        for (int n = 0; n < NST; n++) {
            float dA = __expf(dtv * a[n]);
            h[n]  = fmaf(dA, h[n], dx * sB[t][n]);
            Pr[n] *= dA;
        }
    }
    size_t ob = ((((size_t)z * 2 + b) * NCH + chunk) * NST) * 512 + d;
#pragma unroll
    for (int n = 0; n < NST; n++) {
        P[ob + (size_t)n * 512]    = Pr[n];
        hend[ob + (size_t)n * 512] = h[n];
    }
}

__global__ __launch_bounds__(256) void scan_phase2(
    const float* __restrict__ P, const float* __restrict__ hend,
    float* __restrict__ hinit)
{
    int idx = blockIdx.x * 256 + threadIdx.x;   // 0..32767
    int d = idx & 511;
    int n = (idx >> 9) & 15;
    int b = (idx >> 13) & 1;
    int z = idx >> 14;
    size_t base = ((((size_t)z * 2 + b) * NCH) * NST + n) * 512 + d;
    const size_t cs = (size_t)NST * 512;

    float Pv[NCH], He[NCH];
#pragma unroll
    for (int c = 0; c < NCH; c++) {
        Pv[c] = P[base + (size_t)c * cs];
        He[c] = hend[base + (size_t)c * cs];
    }
    float h = 0.f;
#pragma unroll
    for (int c = 0; c < NCH; c++) {
        hinit[base + (size_t)c * cs] = h;
        h = fmaf(Pv[c], h, He[c]);
    }
}

__global__ __launch_bounds__(256) void scan_phase3(
    const float* __restrict__ dtp, const float* __restrict__ xcp,
    const float* __restrict__ dblp, const float* __restrict__ A_log_l,
    const float* __restrict__ hinit,
    const float* __restrict__ xzp, const float* __restrict__ Dp_l,
    float* __restrict__ yg)
{
    const int chunk = blockIdx.x >> 1;
    const int dg    = blockIdx.x & 1;
    const int b     = blockIdx.y, z = blockIdx.z;
    const int d     = dg * 256 + threadIdx.x;

    __shared__ float sBC[TCH][32];
    const float* dbl_z = dblp + (size_t)z * MM * 48;
    const int base = b * SS + chunk * TCH;
    for (int i = threadIdx.x; i < TCH * 32; i += 256) {
        int t = i >> 5, n = i & 31;
        sBC[t][n] = dbl_z[(size_t)(base + t) * 48 + 16 + n];
    }
    __syncthreads();

    float a[NST];
    const float* al = A_log_l + ((size_t)z * 512 + d) * NST;
#pragma unroll
    for (int n = 0; n < NST; n++) a[n] = -expf(al[n]);

    float h[NST];
    {
        size_t ob = ((((size_t)z * 2 + b) * NCH + chunk) * NST) * 512 + d;
#pragma unroll
        for (int n = 0; n < NST; n++) h[n] = hinit[ob + (size_t)n * 512];
    }
    const float Dv = Dp_l[z * 512 + d];
    const float* dtz = dtp + (size_t)z * MM * 512;
    const float* xcz = xcp + (size_t)z * MM * 512;
    const float* xzz = xzp + (size_t)z * MM * 1024;
    float* ygz = yg + (size_t)z * MM * 512;

    for (int t = 0; t < TCH; t++) {
        int row = base + t;
        float dtv = dtz[(size_t)row * 512 + d];
        float xv  = xcz[(size_t)row * 512 + d];
        float dx  = dtv * xv;
        float y = 0.f;
#pragma unroll
        for (int n = 0; n < NST; n++) {
            float dA = __expf(dtv * a[n]);
            h[n] = fmaf(dA, h[n], dx * sBC[t][n]);
            y = fmaf(h[n], sBC[t][16 + n], y);
        }
        float yfull = fmaf(xv, Dv, y);
        float zv = xzz[(size_t)row * 1024 + 512 + d];
        float sig = 1.f / (1.f + __expf(-zv));
        ygz[(size_t)row * 512 + d] = yfull * zv * sig;
    }
}

// ---------------- host orchestration ----------------
extern "C" void kernel_launch(void* const* d_in, const int* in_sizes, int n_in,
                              void* d_out, int out_size)
{
    const float* x      = (const float*)d_in[0];
    const float* ln_g   = (const float*)d_in[1];
    const float* ln_b   = (const float*)d_in[2];
    const float* inW    = (const float*)d_in[3];
    const float* convW  = (const float*)d_in[4];
    const float* convB  = (const float*)d_in[5];
    const float* xprojW = (const float*)d_in[6];
    const float* dtW    = (const float*)d_in[7];
    const float* dtB    = (const float*)d_in[8];
    const float* A_log  = (const float*)d_in[9];
    const float* Dp     = (const float*)d_in[10];
    const float* outW   = (const float*)d_in[11];
    const float* ipW    = (const float*)d_in[12];
    const float* ipB    = (const float*)d_in[13];
    const float* opW    = (const float*)d_in[14];
    const float* opB    = (const float*)d_in[15];
    const float* fln_g  = (const float*)d_in[16];
    const float* fln_b  = (const float*)d_in[17];

    float* scratch = nullptr;
    cudaGetSymbolAddress((void**)&scratch, g_scratch);
    float* xp   = scratch + OFF_XP;
    float* xn   = scratch + OFF_XN;
    float* xzb  = scratch + OFF_XZ;
    float* xc   = scratch + OFF_XC;
    float* dbl  = scratch + OFF_DBL;
    float* dtb  = scratch + OFF_DT;
    float* yg   = scratch + OFF_YG;
    float* ycat = scratch + OFF_YCAT;
    float* hbuf[2] = { scratch + OFF_H0, scratch + OFF_H1 };
    float* Pb   = scratch + OFF_P;
    float* heb  = scratch + OFF_HEND;
    float* hib  = scratch + OFF_HINIT;

    const float* hin = x;
    for (int l = 0; l < LNUM; l++) {
        const size_t l2 = (size_t)l * 2;

        // xp = hin @ ipW_l^T + ipB_l          (M=2048, N=512, K=512) — tensor
        gemm_mma_kernel<<<dim3(4, 16, 1), 256>>>(
            hin, 512, 0, ipW + (size_t)l * 512 * 512, 512, 0,
            xp, 512, 0, 0, ipB + l * 512, 0, nullptr, 512, 0);

        // per-dir LN over 256 (dir1 reads cols 256.. with flipped S)
        ln_kernel<<<dim3(MM, 2), 256>>>(
            xp, 512, 256, 1, ln_g + l2 * 256, ln_b + l2 * 256, 256,
            xn, 256, (long long)MM * 256, 256);

        // xz = xn @ inW^T                      (N=1024, K=256), both dirs — tensor
        gemm_mma_kernel<<<dim3(8, 16, 2), 256>>>(
            xn, 256, (long long)MM * 256,
            inW + l2 * 1024 * 256, 256, (long long)1024 * 256,
            xzb, 1024, (long long)MM * 1024, 0, nullptr, 0, nullptr, 256, 0);

        // causal dwconv + silu on xz[..,:512]
        conv_silu_kernel<<<(2 * MM * 512) / 256, 256>>>(
            xzb, convW + l2 * 512 * 4, convB + l2 * 512, xc);

        // dbl = xc @ xprojW^T                  (N=48, K=512) — fp32
        gemm2_kernel<64><<<dim3(1, 32, 2), 256>>>(
            xc, 512, (long long)MM * 512,
            xprojW + l2 * 48 * 512, 512, (long long)48 * 512,
            dbl, 48, (long long)MM * 48, 0, nullptr, 0, nullptr, 48, 512, 0);

        // dt = softplus(dbl[:,:16] @ dtW^T + dtB)  (N=512, K=16) — fp32
        gemm2_kernel<128><<<dim3(8, 16, 2), 256>>>(
            dbl, 48, (long long)MM * 48,
            dtW + l2 * 512 * 16, 16, (long long)512 * 16,
            dtb, 512, (long long)MM * 512, 0,
            dtB + l2 * 512, 512, nullptr, 512, 16, FLAG_SOFTPLUS);

        // chunked scan
        scan_phase1<<<dim3(NCH * 2, 2, 2), 256>>>(
            dtb, xc, dbl, A_log + l2 * 512 * NST, Pb, heb);
        scan_phase2<<<128, 256>>>(Pb, heb, hib);
        scan_phase3<<<dim3(NCH * 2, 2, 2), 256>>>(
            dtb, xc, dbl, A_log + l2 * 512 * NST, hib, xzb, Dp + l2 * 512, yg);

        // ycat[:, z*256..] = u + yg @ outW^T   (N=256, K=512), dir1 flip-store — tensor
        gemm_mma_kernel<<<dim3(2, 16, 2), 256>>>(
            yg, 512, (long long)MM * 512,
            outW + l2 * 256 * 512, 512, (long long)256 * 512,
            ycat, 512, 0, 256, nullptr, 0, xp, 512, FLAG_FLIP);

        // h_next = ycat @ opW^T + opB          (N=512, K=512) — tensor
        float* hout = hbuf[l & 1];
        gemm_mma_kernel<<<dim3(4, 16, 1), 256>>>(
            ycat, 512, 0, opW + (size_t)l * 512 * 512, 512, 0,
            hout, 512, 0, 0, opB + l * 512, 0, nullptr, 512, 0);
        hin = hout;
    }

    // final LN over 512 -> d_out
    ln_kernel<<<dim3(MM, 1), 256>>>(
        hin, 512, 0, 0, fln_g, fln_b, 0,
        (float*)d_out, 512, 0, 512);
}

// round 6
// speedup vs baseline: 1.7161x; 1.0122x over previous
#include <cuda_runtime.h>
#include <cuda_bf16.h>
#include <cstdint>

// Problem constants
#define LNUM 2
#define SS   1024
#define MM   2048      // B*S tokens
#define NST  16        // SSM state dim
#define NCH  32        // scan chunks
#define TCH  32        // steps per chunk

#define FLAG_SOFTPLUS 1
#define FLAG_FLIP     2

// ---------------- scratch (static device memory; no allocation) ----------------
#define OFF_XP    0
#define OFF_XN    (OFF_XP   + MM*512)
#define OFF_XZ    (OFF_XN   + 2*MM*256)
#define OFF_XC    (OFF_XZ   + 2*MM*1024)
#define OFF_DBL   (OFF_XC   + 2*MM*512)
#define OFF_DT    (OFF_DBL  + 2*MM*48)
#define OFF_YG    (OFF_DT   + 2*MM*512)
#define OFF_YCAT  (OFF_YG   + 2*MM*512)
#define OFF_H0    (OFF_YCAT + MM*512)
#define OFF_H1    (OFF_H0   + MM*512)
#define OFF_P     (OFF_H1   + MM*512)
#define OFF_HEND  (OFF_P    + 2*2*NCH*NST*512)
#define OFF_HINIT (OFF_HEND + 2*2*NCH*NST*512)
// packed bf16 hi/lo weights (uint32 words stored in float slots)
#define OFF_WPK   (OFF_HINIT + 2*2*NCH*NST*512)
#define WPK_IP    0
#define WPK_IN    (WPK_IP  + 262144)
#define WPK_OUT   (WPK_IN  + 524288)
#define WPK_OP    (WPK_OUT + 262144)
#define WPK_HALF  (WPK_OP  + 262144)     // 1310720 words per (hi|lo) half
#define SCRATCH_TOTAL (OFF_WPK + 2*WPK_HALF)

__device__ float g_scratch[SCRATCH_TOTAL];

// ---------------- bf16 split helpers ----------------
__device__ __forceinline__ uint32_t cvt_pack_bf16(float up, float lo) {
    uint32_t r;
    asm("cvt.rn.bf16x2.f32 %0, %1, %2;" : "=r"(r) : "f"(up), "f"(lo));
    return r;
}
// split pair (e0 = lower half / smaller k, e1 = upper half)
__device__ __forceinline__ void split_pair(float e0, float e1, uint32_t& h, uint32_t& l) {
    h = cvt_pack_bf16(e1, e0);
    float h0 = __uint_as_float(h << 16);
    float h1 = __uint_as_float(h & 0xffff0000u);
    l = cvt_pack_bf16(e1 - h1, e0 - h0);
}

__device__ __forceinline__ void mma_bf16(float4& c, const uint32_t a[4], const uint32_t b[2]) {
    asm volatile(
        "mma.sync.aligned.m16n8k16.row.col.f32.bf16.bf16.f32 "
        "{%0,%1,%2,%3}, {%4,%5,%6,%7}, {%8,%9}, {%0,%1,%2,%3};"
        : "+f"(c.x), "+f"(c.y), "+f"(c.z), "+f"(c.w)
        : "r"(a[0]), "r"(a[1]), "r"(a[2]), "r"(a[3]), "r"(b[0]), "r"(b[1]));
}

// ---------------- weight pre-pack: f32 -> bf16 hi/lo packed pairs ----------------
__global__ __launch_bounds__(256) void pack_bf16_kernel(
    const float* __restrict__ src, uint32_t* __restrict__ dstHi,
    uint32_t* __restrict__ dstLo, int npairs)
{
    int i = blockIdx.x * 256 + threadIdx.x;
    if (i >= npairs) return;
    float2 v = *reinterpret_cast<const float2*>(&src[2 * i]);
    uint32_t h, l;
    split_pair(v.x, v.y, h, l);
    dstHi[i] = h;
    dstLo[i] = l;
}

// ================= bf16-split mma.sync GEMM =================
// C = A(M x K) @ W(N x K)^T (+bias)(+resid, flip-store)
// Block 128x64, BK=16, 256 threads (8 warps: 4m x 2n), warp tile 32x32.
// N multiple of 64, K multiple of 16. W pre-split into packed bf16x2 hi/lo.
// D = Ah*Bh + Ah*Bl + Al*Bh  (fp32 accumulation)
__global__ __launch_bounds__(256) void gemm_bf16_kernel(
    const float* __restrict__ A, int lda, long long sAz,
    const uint32_t* __restrict__ Whi, const uint32_t* __restrict__ Wlo,
    int ldwp, int sWzp,
    float* __restrict__ C, int ldc, long long sCz, int colOffPerZ,
    const float* __restrict__ bias, int sBiasZ,
    const float* __restrict__ resid,
    int K_, int flags)
{
    // frag-major smem: [buf][mat(hi/lo)][tile][words]
    __shared__ uint32_t sA[2][2][8][128];   // 8 m-tiles(16 rows) x 32 lanes x 4 regs
    __shared__ uint32_t sW[2][2][8][64];    // 8 n-tiles(8 cols)  x 32 lanes x 2 regs

    const int tid = threadIdx.x;
    const int wid = tid >> 5, lane = tid & 31;
    const int wm = wid >> 1, wn = wid & 1;   // warp grid 4m x 2n
    const int r = lane >> 2, c = lane & 3;

    const int z = blockIdx.z;
    const int m0 = blockIdx.y * 128, n0 = blockIdx.x * 64;
    const float* Ab = A + (size_t)z * sAz;
    const uint32_t* WhiZ = Whi + (size_t)z * sWzp;
    const uint32_t* WloZ = Wlo + (size_t)z * sWzp;

    float4 acc[2][4];
#pragma unroll
    for (int i = 0; i < 2; i++)
#pragma unroll
        for (int j = 0; j < 4; j++) acc[i][j] = make_float4(0.f, 0.f, 0.f, 0.f);

    const int NC = K_ >> 4;

    // staging
    float4 ar[2];
    uint2 wh, wl;
    const int aRow = tid >> 2, aKq = (tid & 3) << 2;     // + i*64 rows
    const int wN = tid >> 2, wKp = (tid & 3) * 2;        // pair base

    // ---- load chunk 0 ----
#pragma unroll
    for (int i = 0; i < 2; i++)
        ar[i] = *reinterpret_cast<const float4*>(&Ab[(size_t)(m0 + aRow + i * 64) * lda + aKq]);
    wh = *reinterpret_cast<const uint2*>(&WhiZ[(size_t)(n0 + wN) * ldwp + wKp]);
    wl = *reinterpret_cast<const uint2*>(&WloZ[(size_t)(n0 + wN) * ldwp + wKp]);

    // ---- store chunk 0 into buf 0 ----
    {
#pragma unroll
        for (int i = 0; i < 2; i++) {
            int row = aRow + i * 64;
            int mtile = row >> 4, rloc = row & 15;
            int regb = ((aKq & 8) ? 2 : 0) + ((rloc & 8) ? 1 : 0);
            int lane0 = (rloc & 7) * 4 + ((aKq & 7) >> 1);
            uint32_t h01, l01, h23, l23;
            split_pair(ar[i].x, ar[i].y, h01, l01);
            split_pair(ar[i].z, ar[i].w, h23, l23);
            sA[0][0][mtile][lane0 * 4 + regb] = h01;
            sA[0][0][mtile][(lane0 + 1) * 4 + regb] = h23;
            sA[0][1][mtile][lane0 * 4 + regb] = l01;
            sA[0][1][mtile][(lane0 + 1) * 4 + regb] = l23;
        }
        int ntile = wN >> 3, nloc = wN & 7;
        int reg = (wKp & 4) ? 1 : 0;
        int lane0 = nloc * 4 + (wKp & 3);
        sW[0][0][ntile][lane0 * 2 + reg] = wh.x;
        sW[0][0][ntile][(lane0 + 1) * 2 + reg] = wh.y;
        sW[0][1][ntile][lane0 * 2 + reg] = wl.x;
        sW[0][1][ntile][(lane0 + 1) * 2 + reg] = wl.y;
    }
    __syncthreads();

    for (int cc = 0; cc < NC; cc++) {
        const int s = cc & 1;

        // ---- prefetch chunk cc+1 into regs ----
        if (cc + 1 < NC) {
            const int kb = (cc + 1) * 16;
            const int pb = (cc + 1) * 8;
#pragma unroll
            for (int i = 0; i < 2; i++)
                ar[i] = *reinterpret_cast<const float4*>(
                    &Ab[(size_t)(m0 + aRow + i * 64) * lda + kb + aKq]);
            wh = *reinterpret_cast<const uint2*>(&WhiZ[(size_t)(n0 + wN) * ldwp + pb + wKp]);
            wl = *reinterpret_cast<const uint2*>(&WloZ[(size_t)(n0 + wN) * ldwp + pb + wKp]);
        }

        // ---- compute from buf s ----
        {
            uint32_t ah[2][4], al[2][4], bh[4][2], bl[4][2];
#pragma unroll
            for (int mt = 0; mt < 2; mt++) {
                uint4 t = *reinterpret_cast<const uint4*>(&sA[s][0][wm * 2 + mt][lane * 4]);
                ah[mt][0] = t.x; ah[mt][1] = t.y; ah[mt][2] = t.z; ah[mt][3] = t.w;
                uint4 u = *reinterpret_cast<const uint4*>(&sA[s][1][wm * 2 + mt][lane * 4]);
                al[mt][0] = u.x; al[mt][1] = u.y; al[mt][2] = u.z; al[mt][3] = u.w;
            }
#pragma unroll
            for (int nt = 0; nt < 4; nt++) {
                uint2 p = *reinterpret_cast<const uint2*>(&sW[s][0][wn * 4 + nt][lane * 2]);
                bh[nt][0] = p.x; bh[nt][1] = p.y;
                uint2 q = *reinterpret_cast<const uint2*>(&sW[s][1][wn * 4 + nt][lane * 2]);
                bl[nt][0] = q.x; bl[nt][1] = q.y;
            }
#pragma unroll
            for (int mt = 0; mt < 2; mt++)
#pragma unroll
                for (int nt = 0; nt < 4; nt++) {
                    mma_bf16(acc[mt][nt], ah[mt], bh[nt]);
                    mma_bf16(acc[mt][nt], al[mt], bh[nt]);
                    mma_bf16(acc[mt][nt], ah[mt], bl[nt]);
                }
        }

        // ---- store prefetched chunk into other buffer ----
        if (cc + 1 < NC) {
            const int d = s ^ 1;
#pragma unroll
            for (int i = 0; i < 2; i++) {
                int row = aRow + i * 64;
                int mtile = row >> 4, rloc = row & 15;
                int regb = ((aKq & 8) ? 2 : 0) + ((rloc & 8) ? 1 : 0);
                int lane0 = (rloc & 7) * 4 + ((aKq & 7) >> 1);
                uint32_t h01, l01, h23, l23;
                split_pair(ar[i].x, ar[i].y, h01, l01);
                split_pair(ar[i].z, ar[i].w, h23, l23);
                sA[d][0][mtile][lane0 * 4 + regb] = h01;
                sA[d][0][mtile][(lane0 + 1) * 4 + regb] = h23;
                sA[d][1][mtile][lane0 * 4 + regb] = l01;
                sA[d][1][mtile][(lane0 + 1) * 4 + regb] = l23;
            }
            int ntile = wN >> 3, nloc = wN & 7;
            int reg = (wKp & 4) ? 1 : 0;
            int lane0 = nloc * 4 + (wKp & 3);
            sW[d][0][ntile][lane0 * 2 + reg] = wh.x;
            sW[d][0][ntile][(lane0 + 1) * 2 + reg] = wh.y;
            sW[d][1][ntile][lane0 * 2 + reg] = wl.x;
            sW[d][1][ntile][(lane0 + 1) * 2 + reg] = wl.y;
        }
        __syncthreads();
    }

    // ---- epilogue ----
    const int coff = colOffPerZ * z;
#pragma unroll
    for (int mt = 0; mt < 2; mt++) {
        int mA = m0 + wm * 32 + mt * 16 + r;
        int mB = mA + 8;
        int rA = mA, rB = mB;
        if ((flags & FLAG_FLIP) && z == 1) {
            rA = (mA & ~(SS - 1)) + ((SS - 1) - (mA & (SS - 1)));
            rB = (mB & ~(SS - 1)) + ((SS - 1) - (mB & (SS - 1)));
        }
        float* rowA = C + (size_t)z * sCz + (size_t)rA * ldc + coff;
        float* rowB = C + (size_t)z * sCz + (size_t)rB * ldc + coff;
        const float* resA = resid ? (resid + (size_t)rA * ldc + coff) : nullptr;
        const float* resB = resid ? (resid + (size_t)rB * ldc + coff) : nullptr;
#pragma unroll
        for (int nt = 0; nt < 4; nt++) {
            int n = n0 + wn * 32 + nt * 8 + 2 * c;
            float2 vA = make_float2(acc[mt][nt].x, acc[mt][nt].y);
            float2 vB = make_float2(acc[mt][nt].z, acc[mt][nt].w);
            if (bias) {
                float2 bv = *reinterpret_cast<const float2*>(&bias[z * sBiasZ + n]);
                vA.x += bv.x; vA.y += bv.y;
                vB.x += bv.x; vB.y += bv.y;
            }
            if (flags & FLAG_SOFTPLUS) {
                vA.x = (vA.x > 20.f) ? vA.x : log1pf(__expf(vA.x));
                vA.y = (vA.y > 20.f) ? vA.y : log1pf(__expf(vA.y));
                vB.x = (vB.x > 20.f) ? vB.x : log1pf(__expf(vB.x));
                vB.y = (vB.y > 20.f) ? vB.y : log1pf(__expf(vB.y));
            }
            if (resA) {
                float2 qa = *reinterpret_cast<const float2*>(&resA[n]);
                float2 qb = *reinterpret_cast<const float2*>(&resB[n]);
                vA.x += qa.x; vA.y += qa.y;
                vB.x += qb.x; vB.y += qb.y;
            }
            *reinterpret_cast<float2*>(&rowA[n]) = vA;
            *reinterpret_cast<float2*>(&rowB[n]) = vB;
        }
    }
}

// ================= f32x2 fp32 GEMM (small shapes: xproj N=48, dt K=16) =================
#define PACK_DUP(dst, s) asm("mov.b64 %0, {%1, %1};" : "=l"(dst) : "f"(s))
#define FMA2(acc, a, b)  asm("fma.rn.f32x2 %0, %1, %2, %0;" : "+l"(acc) : "l"(a), "l"(b))
#define UNPACK2(lo, hi, v) asm("mov.b64 {%0, %1}, %2;" : "=f"(lo), "=f"(hi) : "l"(v))

template<int BMT>
__global__ __launch_bounds__(256, 2) void gemm2_kernel(
    const float* __restrict__ A, int lda, long long sAz,
    const float* __restrict__ W, int ldw, long long sWz,
    float* __restrict__ C, int ldc, long long sCz, int colOffPerZ,
    const float* __restrict__ bias, int sBiasZ,
    const float* __restrict__ resid,
    int N_, int K_, int flags)
{
    constexpr int MT = BMT / 16;
    constexpr int MP = MT / 2;
    constexpr int AL = BMT + 4;
    constexpr int NA = BMT / 64;

    const int z  = blockIdx.z;
    const float* Ab = A + (size_t)z * sAz;
    const float* Wb = W + (size_t)z * sWz;
    const int m0 = blockIdx.y * BMT;
    const int n0 = blockIdx.x * 64;

    __shared__ __align__(16) float As[16][AL];
    __shared__ __align__(16) float Ws[16][68];

    unsigned long long acc[MP][4];
#pragma unroll
    for (int i = 0; i < MP; i++)
#pragma unroll
        for (int j = 0; j < 4; j++) acc[i][j] = 0ULL;

    const int tid = threadIdx.x;
    const int tx = tid & 15, ty = tid >> 4;

    float4 aFrag[NA];
    float4 wFrag;
    {
#pragma unroll
        for (int i = 0; i < NA; i++) {
            int lin = tid + i * 256;
            int m = lin >> 2, kq = (lin & 3) << 2;
            aFrag[i] = *reinterpret_cast<const float4*>(
                &Ab[(size_t)(m0 + m) * lda + kq]);
        }
        int n = tid >> 2, kq = (tid & 3) << 2;
        wFrag = make_float4(0.f, 0.f, 0.f, 0.f);
        if (n0 + n < N_)
            wFrag = *reinterpret_cast<const float4*>(
                &Wb[(size_t)(n0 + n) * ldw + kq]);
    }

    for (int k0 = 0; k0 < K_; k0 += 16) {
#pragma unroll
        for (int i = 0; i < NA; i++) {
            int lin = tid + i * 256;
            int m = lin >> 2, kq = (lin & 3) << 2;
            As[kq + 0][m] = aFrag[i].x; As[kq + 1][m] = aFrag[i].y;
            As[kq + 2][m] = aFrag[i].z; As[kq + 3][m] = aFrag[i].w;
        }
        {
            int n = tid >> 2, kq = (tid & 3) << 2;
            Ws[kq + 0][n] = wFrag.x; Ws[kq + 1][n] = wFrag.y;
            Ws[kq + 2][n] = wFrag.z; Ws[kq + 3][n] = wFrag.w;
        }
        __syncthreads();

        if (k0 + 16 < K_) {
#pragma unroll
            for (int i = 0; i < NA; i++) {
                int lin = tid + i * 256;
                int m = lin >> 2, kq = (lin & 3) << 2;
                aFrag[i] = *reinterpret_cast<const float4*>(
                    &Ab[(size_t)(m0 + m) * lda + k0 + 16 + kq]);
            }
            int n = tid >> 2, kq = (tid & 3) << 2;
            wFrag = make_float4(0.f, 0.f, 0.f, 0.f);
            if (n0 + n < N_)
                wFrag = *reinterpret_cast<const float4*>(
                    &Wb[(size_t)(n0 + n) * ldw + k0 + 16 + kq]);
        }

#pragma unroll
        for (int k = 0; k < 16; k++) {
            unsigned long long ap[MP];
            {
                ulonglong2 q0 = *reinterpret_cast<const ulonglong2*>(&As[k][ty * MT]);
                ap[0] = q0.x; ap[1] = q0.y;
                if (MP == 4) {
                    ulonglong2 q1 = *reinterpret_cast<const ulonglong2*>(&As[k][ty * MT + 4]);
                    ap[2] = q1.x; ap[3] = q1.y;
                }
            }
            float4 wv = *reinterpret_cast<const float4*>(&Ws[k][tx * 4]);
            unsigned long long wd[4];
            PACK_DUP(wd[0], wv.x); PACK_DUP(wd[1], wv.y);
            PACK_DUP(wd[2], wv.z); PACK_DUP(wd[3], wv.w);
#pragma unroll
            for (int i = 0; i < MP; i++)
#pragma unroll
                for (int j = 0; j < 4; j++)
                    FMA2(acc[i][j], ap[i], wd[j]);
        }
        __syncthreads();
    }

    const int coff = colOffPerZ * z;
#pragma unroll
    for (int i = 0; i < MP; i++) {
        int mA = m0 + ty * MT + 2 * i;
        int mB = mA + 1;
        int rA = mA, rB = mB;
        if ((flags & FLAG_FLIP) && z == 1) {
            rA = (mA & ~(SS - 1)) + ((SS - 1) - (mA & (SS - 1)));
            rB = (mB & ~(SS - 1)) + ((SS - 1) - (mB & (SS - 1)));
        }
        float* crowA = C + (size_t)z * sCz + (size_t)rA * ldc + coff;
        float* crowB = C + (size_t)z * sCz + (size_t)rB * ldc + coff;
#pragma unroll
        for (int j = 0; j < 4; j++) {
            int n = n0 + tx * 4 + j;
            if (n < N_) {
                float vA, vB;
                UNPACK2(vA, vB, acc[i][j]);
                if (bias) {
                    float bv = bias[z * sBiasZ + n];
                    vA += bv; vB += bv;
                }
                if (flags & FLAG_SOFTPLUS) {
                    vA = (vA > 20.f) ? vA : log1pf(__expf(vA));
                    vB = (vB > 20.f) ? vB : log1pf(__expf(vB));
                }
                if (resid) {
                    vA += resid[(size_t)rA * ldc + coff + n];
                    vB += resid[(size_t)rB * ldc + coff + n];
                }
                crowA[n] = vA;
                crowB[n] = vB;
            }
        }
    }
}

// ---------------- LayerNorm ----------------
__device__ __forceinline__ void block_reduce_2(float& s1, float& s2)
{
    __shared__ float sh1[8], sh2[8];
#pragma unroll
    for (int o = 16; o > 0; o >>= 1) {
        s1 += __shfl_xor_sync(0xffffffffu, s1, o);
        s2 += __shfl_xor_sync(0xffffffffu, s2, o);
    }
    int lane = threadIdx.x & 31, wid = threadIdx.x >> 5;
    if (lane == 0) { sh1[wid] = s1; sh2[wid] = s2; }
    __syncthreads();
    if (threadIdx.x == 0) {
        float a = 0.f, b = 0.f;
#pragma unroll
        for (int i = 0; i < 8; i++) { a += sh1[i]; b += sh2[i]; }
        sh1[0] = a; sh2[0] = b;
    }
    __syncthreads();
    s1 = sh1[0]; s2 = sh2[0];
}

__global__ __launch_bounds__(256) void ln_kernel(
    const float* __restrict__ src, int ldsrc, int colOffPerZ, int flipz,
    const float* __restrict__ g, const float* __restrict__ bta, int gbStrideZ,
    float* __restrict__ dst, int lddst, long long dstStrideZ, int Dvec)
{
    const int m = blockIdx.x, z = blockIdx.y;
    int srow = m;
    if (flipz && z == 1)
        srow = (m & ~(SS - 1)) + ((SS - 1) - (m & (SS - 1)));
    const float* sp = src + (size_t)srow * ldsrc + colOffPerZ * z;
    const int tid = threadIdx.x;

    float v0 = sp[tid];
    float v1 = (Dvec > 256) ? sp[tid + 256] : 0.f;
    float s1 = v0 + v1, s2 = v0 * v0 + v1 * v1;
    block_reduce_2(s1, s2);

    const float invD = 1.f / (float)Dvec;
    float mean = s1 * invD;
    float var  = s2 * invD - mean * mean;
    float inv  = rsqrtf(var + 1e-5f);

    const float* gz = g + z * gbStrideZ;
    const float* bz = bta + z * gbStrideZ;
    float* dp = dst + (size_t)z * dstStrideZ + (size_t)m * lddst;
    dp[tid] = (v0 - mean) * inv * gz[tid] + bz[tid];
    if (Dvec > 256)
        dp[tid + 256] = (v1 - mean) * inv * gz[tid + 256] + bz[tid + 256];
}

// ---------------- causal depthwise conv (K=4) + SiLU ----------------
__global__ __launch_bounds__(256) void conv_silu_kernel(
    const float* __restrict__ xz,   // [2][MM][1024], cols 0..511 are xc-raw
    const float* __restrict__ cW,   // [2][512][4]
    const float* __restrict__ cB,   // [2][512]
    float* __restrict__ xc)         // [2][MM][512]
{
    int idx = blockIdx.x * 256 + threadIdx.x;      // < 2*MM*512 = 2^21
    int d   = idx & 511;
    int row = (idx >> 9) & (MM - 1);
    int z   = idx >> 20;
    int s   = row & (SS - 1);
    int bs0 = row - s;

    const float4 wv = *reinterpret_cast<const float4*>(&cW[((size_t)z * 512 + d) * 4]);
    const float w[4] = {wv.x, wv.y, wv.z, wv.w};
    float acc = cB[z * 512 + d];
    const float* xzz = xz + (size_t)z * MM * 1024;
#pragma unroll
    for (int k = 0; k < 4; k++) {
        int sp = s - 3 + k;
        if (sp >= 0) acc += w[k] * xzz[(size_t)(bs0 + sp) * 1024 + d];
    }
    float sig = 1.f / (1.f + __expf(-acc));
    xc[(size_t)z * MM * 512 + (size_t)row * 512 + d] = acc * sig;
}

// ---------------- chunked SSM scan ----------------
__global__ __launch_bounds__(256) void scan_phase1(
    const float* __restrict__ dtp, const float* __restrict__ xcp,
    const float* __restrict__ dblp, const float* __restrict__ A_log_l,
    float* __restrict__ P, float* __restrict__ hend)
{
    const int chunk = blockIdx.x >> 1;
    const int dg    = blockIdx.x & 1;
    const int b     = blockIdx.y, z = blockIdx.z;
    const int d     = dg * 256 + threadIdx.x;

    __shared__ float sB[TCH][NST];
    const float* dbl_z = dblp + (size_t)z * MM * 48;
    const int base = b * SS + chunk * TCH;
    for (int i = threadIdx.x; i < TCH * NST; i += 256) {
        int t = i >> 4, n = i & 15;
        sB[t][n] = dbl_z[(size_t)(base + t) * 48 + 16 + n];
    }
    __syncthreads();

    float a[NST];
    const float* al = A_log_l + ((size_t)z * 512 + d) * NST;
#pragma unroll
    for (int n = 0; n < NST; n++) a[n] = -expf(al[n]);

    float h[NST], Pr[NST];
#pragma unroll
    for (int n = 0; n < NST; n++) { h[n] = 0.f; Pr[n] = 1.f; }

    const float* dtz = dtp + (size_t)z * MM * 512;
    const float* xcz = xcp + (size_t)z * MM * 512;
    for (int t = 0; t < TCH; t++) {
        int row = base + t;
        float dtv = dtz[(size_t)row * 512 + d];
        float xv  = xcz[(size_t)row * 512 + d];
        float dx  = dtv * xv;
#pragma unroll
        for (int n = 0; n < NST; n++) {
            float dA = __expf(dtv * a[n]);
            h[n]  = fmaf(dA, h[n], dx * sB[t][n]);
            Pr[n] *= dA;
        }
    }
    size_t ob = ((((size_t)z * 2 + b) * NCH + chunk) * NST) * 512 + d;
#pragma unroll
    for (int n = 0; n < NST; n++) {
        P[ob + (size_t)n * 512]    = Pr[n];
        hend[ob + (size_t)n * 512] = h[n];
    }
}

__global__ __launch_bounds__(256) void scan_phase2(
    const float* __restrict__ P, const float* __restrict__ hend,
    float* __restrict__ hinit)
{
    int idx = blockIdx.x * 256 + threadIdx.x;   // 0..32767
    int d = idx & 511;
    int n = (idx >> 9) & 15;
    int b = (idx >> 13) & 1;
    int z = idx >> 14;
    size_t base = ((((size_t)z * 2 + b) * NCH) * NST + n) * 512 + d;
    const size_t cs = (size_t)NST * 512;

    float Pv[NCH], He[NCH];
#pragma unroll
    for (int c = 0; c < NCH; c++) {
        Pv[c] = P[base + (size_t)c * cs];
        He[c] = hend[base + (size_t)c * cs];
    }
    float h = 0.f;
#pragma unroll
    for (int c = 0; c < NCH; c++) {
        hinit[base + (size_t)c * cs] = h;
        h = fmaf(Pv[c], h, He[c]);
    }
}

__global__ __launch_bounds__(256) void scan_phase3(
    const float* __restrict__ dtp, const float* __restrict__ xcp,
    const float* __restrict__ dblp, const float* __restrict__ A_log_l,
    const float* __restrict__ hinit,
    const float* __restrict__ xzp, const float* __restrict__ Dp_l,
    float* __restrict__ yg)
{
    const int chunk = blockIdx.x >> 1;
    const int dg    = blockIdx.x & 1;
    const int b     = blockIdx.y, z = blockIdx.z;
    const int d     = dg * 256 + threadIdx.x;

    __shared__ float sBC[TCH][32];
    const float* dbl_z = dblp + (size_t)z * MM * 48;
    const int base = b * SS + chunk * TCH;
    for (int i = threadIdx.x; i < TCH * 32; i += 256) {
        int t = i >> 5, n = i & 31;
        sBC[t][n] = dbl_z[(size_t)(base + t) * 48 + 16 + n];
    }
    __syncthreads();

    float a[NST];
    const float* al = A_log_l + ((size_t)z * 512 + d) * NST;
#pragma unroll
    for (int n = 0; n < NST; n++) a[n] = -expf(al[n]);

    float h[NST];
    {
        size_t ob = ((((size_t)z * 2 + b) * NCH + chunk) * NST) * 512 + d;
#pragma unroll
        for (int n = 0; n < NST; n++) h[n] = hinit[ob + (size_t)n * 512];
    }
    const float Dv = Dp_l[z * 512 + d];
    const float* dtz = dtp + (size_t)z * MM * 512;
    const float* xcz = xcp + (size_t)z * MM * 512;
    const float* xzz = xzp + (size_t)z * MM * 1024;
    float* ygz = yg + (size_t)z * MM * 512;

    for (int t = 0; t < TCH; t++) {
        int row = base + t;
        float dtv = dtz[(size_t)row * 512 + d];
        float xv  = xcz[(size_t)row * 512 + d];
        float dx  = dtv * xv;
        float y = 0.f;
#pragma unroll
        for (int n = 0; n < NST; n++) {
            float dA = __expf(dtv * a[n]);
            h[n] = fmaf(dA, h[n], dx * sBC[t][n]);
            y = fmaf(h[n], sBC[t][16 + n], y);
        }
        float yfull = fmaf(xv, Dv, y);
        float zv = xzz[(size_t)row * 1024 + 512 + d];
        float sig = 1.f / (1.f + __expf(-zv));
        ygz[(size_t)row * 512 + d] = yfull * zv * sig;
    }
}

// ---------------- host orchestration ----------------
extern "C" void kernel_launch(void* const* d_in, const int* in_sizes, int n_in,
                              void* d_out, int out_size)
{
    const float* x      = (const float*)d_in[0];
    const float* ln_g   = (const float*)d_in[1];
    const float* ln_b   = (const float*)d_in[2];
    const float* inW    = (const float*)d_in[3];
    const float* convW  = (const float*)d_in[4];
    const float* convB  = (const float*)d_in[5];
    const float* xprojW = (const float*)d_in[6];
    const float* dtW    = (const float*)d_in[7];
    const float* dtB    = (const float*)d_in[8];
    const float* A_log  = (const float*)d_in[9];
    const float* Dp     = (const float*)d_in[10];
    const float* outW   = (const float*)d_in[11];
    const float* ipW    = (const float*)d_in[12];
    const float* ipB    = (const float*)d_in[13];
    const float* opW    = (const float*)d_in[14];
    const float* opB    = (const float*)d_in[15];
    const float* fln_g  = (const float*)d_in[16];
    const float* fln_b  = (const float*)d_in[17];

    float* scratch = nullptr;
    cudaGetSymbolAddress((void**)&scratch, g_scratch);
    float* xp   = scratch + OFF_XP;
    float* xn   = scratch + OFF_XN;
    float* xzb  = scratch + OFF_XZ;
    float* xc   = scratch + OFF_XC;
    float* dbl  = scratch + OFF_DBL;
    float* dtb  = scratch + OFF_DT;
    float* yg   = scratch + OFF_YG;
    float* ycat = scratch + OFF_YCAT;
    float* hbuf[2] = { scratch + OFF_H0, scratch + OFF_H1 };
    float* Pb   = scratch + OFF_P;
    float* heb  = scratch + OFF_HEND;
    float* hib  = scratch + OFF_HINIT;

    uint32_t* wpk = (uint32_t*)(scratch + OFF_WPK);
    uint32_t* ipH = wpk + WPK_IP;  uint32_t* ipL = wpk + WPK_HALF + WPK_IP;
    uint32_t* inH = wpk + WPK_IN;  uint32_t* inL = wpk + WPK_HALF + WPK_IN;
    uint32_t* otH = wpk + WPK_OUT; uint32_t* otL = wpk + WPK_HALF + WPK_OUT;
    uint32_t* opH = wpk + WPK_OP;  uint32_t* opL = wpk + WPK_HALF + WPK_OP;

    // ---- pre-split all weights into packed bf16 hi/lo ----
    pack_bf16_kernel<<<1024, 256>>>(ipW,  ipH, ipL, 262144);
    pack_bf16_kernel<<<2048, 256>>>(inW,  inH, inL, 524288);
    pack_bf16_kernel<<<1024, 256>>>(outW, otH, otL, 262144);
    pack_bf16_kernel<<<1024, 256>>>(opW,  opH, opL, 262144);

    const float* hin = x;
    for (int l = 0; l < LNUM; l++) {
        const size_t l2 = (size_t)l * 2;

        // xp = hin @ ipW_l^T + ipB_l          (M=2048, N=512, K=512) — tensor
        gemm_bf16_kernel<<<dim3(8, 16, 1), 256>>>(
            hin, 512, 0, ipH + (size_t)l * 131072, ipL + (size_t)l * 131072, 256, 0,
            xp, 512, 0, 0, ipB + l * 512, 0, nullptr, 512, 0);

        // per-dir LN over 256 (dir1 reads cols 256.. with flipped S)
        ln_kernel<<<dim3(MM, 2), 256>>>(
            xp, 512, 256, 1, ln_g + l2 * 256, ln_b + l2 * 256, 256,
            xn, 256, (long long)MM * 256, 256);

        // xz = xn @ inW^T                      (N=1024, K=256), both dirs — tensor
        gemm_bf16_kernel<<<dim3(16, 16, 2), 256>>>(
            xn, 256, (long long)MM * 256,
            inH + l2 * 131072, inL + l2 * 131072, 128, 131072,
            xzb, 1024, (long long)MM * 1024, 0, nullptr, 0, nullptr, 256, 0);

        // causal dwconv + silu on xz[..,:512]
        conv_silu_kernel<<<(2 * MM * 512) / 256, 256>>>(
            xzb, convW + l2 * 512 * 4, convB + l2 * 512, xc);

        // dbl = xc @ xprojW^T                  (N=48, K=512) — fp32
        gemm2_kernel<64><<<dim3(1, 32, 2), 256>>>(
            xc, 512, (long long)MM * 512,
            xprojW + l2 * 48 * 512, 512, (long long)48 * 512,
            dbl, 48, (long long)MM * 48, 0, nullptr, 0, nullptr, 48, 512, 0);

        // dt = softplus(dbl[:,:16] @ dtW^T + dtB)  (N=512, K=16) — fp32
        gemm2_kernel<128><<<dim3(8, 16, 2), 256>>>(
            dbl, 48, (long long)MM * 48,
            dtW + l2 * 512 * 16, 16, (long long)512 * 16,
            dtb, 512, (long long)MM * 512, 0,
            dtB + l2 * 512, 512, nullptr, 512, 16, FLAG_SOFTPLUS);

        // chunked scan
        scan_phase1<<<dim3(NCH * 2, 2, 2), 256>>>(
            dtb, xc, dbl, A_log + l2 * 512 * NST, Pb, heb);
        scan_phase2<<<128, 256>>>(Pb, heb, hib);
        scan_phase3<<<dim3(NCH * 2, 2, 2), 256>>>(
            dtb, xc, dbl, A_log + l2 * 512 * NST, hib, xzb, Dp + l2 * 512, yg);

        // ycat[:, z*256..] = u + yg @ outW^T   (N=256, K=512), dir1 flip-store — tensor
        gemm_bf16_kernel<<<dim3(4, 16, 2), 256>>>(
            yg, 512, (long long)MM * 512,
            otH + l2 * 65536, otL + l2 * 65536, 256, 65536,
            ycat, 512, 0, 256, nullptr, 0, xp, 512, FLAG_FLIP);

        // h_next = ycat @ opW^T + opB          (N=512, K=512) — tensor
        float* hout = hbuf[l & 1];
        gemm_bf16_kernel<<<dim3(8, 16, 1), 256>>>(
            ycat, 512, 0, opH + (size_t)l * 131072, opL + (size_t)l * 131072, 256, 0,
            hout, 512, 0, 0, opB + l * 512, 0, nullptr, 512, 0);
        hin = hout;
    }

    // final LN over 512 -> d_out
    ln_kernel<<<dim3(MM, 1), 256>>>(
        hin, 512, 0, 0, fln_g, fln_b, 0,
        (float*)d_out, 512, 0, 512);
}

// round 7
// speedup vs baseline: 1.8639x; 1.0862x over previous
#include <cuda_runtime.h>
#include <cuda_bf16.h>
#include <cstdint>

// Problem constants
#define LNUM 2
#define SS   1024
#define MM   2048      // B*S tokens
#define NST  16        // SSM state dim
#define NCH  32        // scan chunks
#define TCH  32        // steps per chunk

#define FLAG_SOFTPLUS 1
#define FLAG_FLIP     2

// ---------------- scratch (static device memory; no allocation) ----------------
#define OFF_XP    0
#define OFF_XN    (OFF_XP   + MM*512)
#define OFF_XZ    (OFF_XN   + 2*MM*256)
#define OFF_XC    (OFF_XZ   + 2*MM*1024)
#define OFF_DBL   (OFF_XC   + 2*MM*512)
#define OFF_YG    (OFF_DBL  + 2*MM*48)
#define OFF_YCAT  (OFF_YG   + 2*MM*512)
#define OFF_H0    (OFF_YCAT + MM*512)
#define OFF_H1    (OFF_H0   + MM*512)
#define OFF_P     (OFF_H1   + MM*512)
#define OFF_HEND  (OFF_P    + 2*2*NCH*NST*512)
#define OFF_HINIT (OFF_HEND + 2*2*NCH*NST*512)
// packed bf16 hi/lo weights (uint32 words stored in float slots)
#define OFF_WPK   (OFF_HINIT + 2*2*NCH*NST*512)
#define WPK_IP    0
#define WPK_IN    (WPK_IP  + 262144)
#define WPK_OUT   (WPK_IN  + 524288)
#define WPK_OP    (WPK_OUT + 262144)
#define WPK_HALF  (WPK_OP  + 262144)     // 1310720 words per (hi|lo) half
#define SCRATCH_TOTAL (OFF_WPK + 2*WPK_HALF)

__device__ float g_scratch[SCRATCH_TOTAL];

// ---------------- bf16 split helpers ----------------
__device__ __forceinline__ uint32_t cvt_pack_bf16(float up, float lo) {
    uint32_t r;
    asm("cvt.rn.bf16x2.f32 %0, %1, %2;" : "=r"(r) : "f"(up), "f"(lo));
    return r;
}
// split pair (e0 = lower half / smaller k, e1 = upper half)
__device__ __forceinline__ void split_pair(float e0, float e1, uint32_t& h, uint32_t& l) {
    h = cvt_pack_bf16(e1, e0);
    float h0 = __uint_as_float(h << 16);
    float h1 = __uint_as_float(h & 0xffff0000u);
    l = cvt_pack_bf16(e1 - h1, e0 - h0);
}

__device__ __forceinline__ void mma_bf16(float4& c, const uint32_t a[4], const uint32_t b[2]) {
    asm volatile(
        "mma.sync.aligned.m16n8k16.row.col.f32.bf16.bf16.f32 "
        "{%0,%1,%2,%3}, {%4,%5,%6,%7}, {%8,%9}, {%0,%1,%2,%3};"
        : "+f"(c.x), "+f"(c.y), "+f"(c.z), "+f"(c.w)
        : "r"(a[0]), "r"(a[1]), "r"(a[2]), "r"(a[3]), "r"(b[0]), "r"(b[1]));
}

// ---------------- merged weight pre-pack: all 4 weight tensors in one launch ----------------
__global__ __launch_bounds__(256) void pack_all_kernel(
    const float* __restrict__ ipW, const float* __restrict__ inW,
    const float* __restrict__ outW, const float* __restrict__ opW,
    uint32_t* __restrict__ dstHi, uint32_t* __restrict__ dstLo)
{
    int i = blockIdx.x * 256 + threadIdx.x;
    if (i >= WPK_HALF) return;
    const float* src;
    int local;
    if (i < WPK_IN)            { src = ipW;  local = i - WPK_IP; }
    else if (i < WPK_OUT)      { src = inW;  local = i - WPK_IN; }
    else if (i < WPK_OP)       { src = outW; local = i - WPK_OUT; }
    else                       { src = opW;  local = i - WPK_OP; }
    float2 v = *reinterpret_cast<const float2*>(&src[2 * local]);
    uint32_t h, l;
    split_pair(v.x, v.y, h, l);
    dstHi[i] = h;
    dstLo[i] = l;
}

// ================= bf16-split mma.sync GEMM =================
// C = A(M x K) @ W(N x K)^T (+bias)(+resid, flip-store)
// Block 128x64, BK=16, 256 threads (8 warps: 4m x 2n), warp tile 32x32.
// N multiple of 64, K multiple of 16. W pre-split into packed bf16x2 hi/lo.
// D = Ah*Bh + Ah*Bl + Al*Bh  (fp32 accumulation)
__global__ __launch_bounds__(256, 2) void gemm_bf16_kernel(
    const float* __restrict__ A, int lda, long long sAz,
    const uint32_t* __restrict__ Whi, const uint32_t* __restrict__ Wlo,
    int ldwp, int sWzp,
    float* __restrict__ C, int ldc, long long sCz, int colOffPerZ,
    const float* __restrict__ bias, int sBiasZ,
    const float* __restrict__ resid,
    int K_, int flags)
{
    // frag-major smem: [buf][mat(hi/lo)][tile][words]
    __shared__ uint32_t sA[2][2][8][128];   // 8 m-tiles(16 rows) x 32 lanes x 4 regs
    __shared__ uint32_t sW[2][2][8][64];    // 8 n-tiles(8 cols)  x 32 lanes x 2 regs

    const int tid = threadIdx.x;
    const int wid = tid >> 5, lane = tid & 31;
    const int wm = wid >> 1, wn = wid & 1;   // warp grid 4m x 2n
    const int r = lane >> 2, c = lane & 3;

    const int z = blockIdx.z;
    const int m0 = blockIdx.y * 128, n0 = blockIdx.x * 64;
    const float* Ab = A + (size_t)z * sAz;
    const uint32_t* WhiZ = Whi + (size_t)z * sWzp;
    const uint32_t* WloZ = Wlo + (size_t)z * sWzp;

    float4 acc[2][4];
#pragma unroll
    for (int i = 0; i < 2; i++)
#pragma unroll
        for (int j = 0; j < 4; j++) acc[i][j] = make_float4(0.f, 0.f, 0.f, 0.f);

    const int NC = K_ >> 4;

    // staging
    float4 ar[2];
    uint2 wh, wl;
    const int aRow = tid >> 2, aKq = (tid & 3) << 2;     // + i*64 rows
    const int wN = tid >> 2, wKp = (tid & 3) * 2;        // pair base

    // ---- load chunk 0 ----
#pragma unroll
    for (int i = 0; i < 2; i++)
        ar[i] = *reinterpret_cast<const float4*>(&Ab[(size_t)(m0 + aRow + i * 64) * lda + aKq]);
    wh = *reinterpret_cast<const uint2*>(&WhiZ[(size_t)(n0 + wN) * ldwp + wKp]);
    wl = *reinterpret_cast<const uint2*>(&WloZ[(size_t)(n0 + wN) * ldwp + wKp]);

    // ---- store chunk 0 into buf 0 ----
    {
#pragma unroll
        for (int i = 0; i < 2; i++) {
            int row = aRow + i * 64;
            int mtile = row >> 4, rloc = row & 15;
            int regb = ((aKq & 8) ? 2 : 0) + ((rloc & 8) ? 1 : 0);
            int lane0 = (rloc & 7) * 4 + ((aKq & 7) >> 1);
            uint32_t h01, l01, h23, l23;
            split_pair(ar[i].x, ar[i].y, h01, l01);
            split_pair(ar[i].z, ar[i].w, h23, l23);
            sA[0][0][mtile][lane0 * 4 + regb] = h01;
            sA[0][0][mtile][(lane0 + 1) * 4 + regb] = h23;
            sA[0][1][mtile][lane0 * 4 + regb] = l01;
            sA[0][1][mtile][(lane0 + 1) * 4 + regb] = l23;
        }
        int ntile = wN >> 3, nloc = wN & 7;
        int reg = (wKp & 4) ? 1 : 0;
        int lane0 = nloc * 4 + (wKp & 3);
        sW[0][0][ntile][lane0 * 2 + reg] = wh.x;
        sW[0][0][ntile][(lane0 + 1) * 2 + reg] = wh.y;
        sW[0][1][ntile][lane0 * 2 + reg] = wl.x;
        sW[0][1][ntile][(lane0 + 1) * 2 + reg] = wl.y;
    }
    __syncthreads();

    for (int cc = 0; cc < NC; cc++) {
        const int s = cc & 1;

        // ---- prefetch chunk cc+1 into regs ----
        if (cc + 1 < NC) {
            const int kb = (cc + 1) * 16;
            const int pb = (cc + 1) * 8;
#pragma unroll
            for (int i = 0; i < 2; i++)
                ar[i] = *reinterpret_cast<const float4*>(
                    &Ab[(size_t)(m0 + aRow + i * 64) * lda + kb + aKq]);
            wh = *reinterpret_cast<const uint2*>(&WhiZ[(size_t)(n0 + wN) * ldwp + pb + wKp]);
            wl = *reinterpret_cast<const uint2*>(&WloZ[(size_t)(n0 + wN) * ldwp + pb + wKp]);
        }

        // ---- compute from buf s ----
        {
            uint32_t ah[2][4], al[2][4], bh[4][2], bl[4][2];
#pragma unroll
            for (int mt = 0; mt < 2; mt++) {
                uint4 t = *reinterpret_cast<const uint4*>(&sA[s][0][wm * 2 + mt][lane * 4]);
                ah[mt][0] = t.x; ah[mt][1] = t.y; ah[mt][2] = t.z; ah[mt][3] = t.w;
                uint4 u = *reinterpret_cast<const uint4*>(&sA[s][1][wm * 2 + mt][lane * 4]);
                al[mt][0] = u.x; al[mt][1] = u.y; al[mt][2] = u.z; al[mt][3] = u.w;
            }
#pragma unroll
            for (int nt = 0; nt < 4; nt++) {
                uint2 p = *reinterpret_cast<const uint2*>(&sW[s][0][wn * 4 + nt][lane * 2]);
                bh[nt][0] = p.x; bh[nt][1] = p.y;
                uint2 q = *reinterpret_cast<const uint2*>(&sW[s][1][wn * 4 + nt][lane * 2]);
                bl[nt][0] = q.x; bl[nt][1] = q.y;
            }
#pragma unroll
            for (int mt = 0; mt < 2; mt++)
#pragma unroll
                for (int nt = 0; nt < 4; nt++) {
                    mma_bf16(acc[mt][nt], ah[mt], bh[nt]);
                    mma_bf16(acc[mt][nt], al[mt], bh[nt]);
                    mma_bf16(acc[mt][nt], ah[mt], bl[nt]);
                }
        }

        // ---- store prefetched chunk into other buffer ----
        if (cc + 1 < NC) {
            const int d = s ^ 1;
#pragma unroll
            for (int i = 0; i < 2; i++) {
                int row = aRow + i * 64;
                int mtile = row >> 4, rloc = row & 15;
                int regb = ((aKq & 8) ? 2 : 0) + ((rloc & 8) ? 1 : 0);
                int lane0 = (rloc & 7) * 4 + ((aKq & 7) >> 1);
                uint32_t h01, l01, h23, l23;
                split_pair(ar[i].x, ar[i].y, h01, l01);
                split_pair(ar[i].z, ar[i].w, h23, l23);
                sA[d][0][mtile][lane0 * 4 + regb] = h01;
                sA[d][0][mtile][(lane0 + 1) * 4 + regb] = h23;
                sA[d][1][mtile][lane0 * 4 + regb] = l01;
                sA[d][1][mtile][(lane0 + 1) * 4 + regb] = l23;
            }
            int ntile = wN >> 3, nloc = wN & 7;
            int reg = (wKp & 4) ? 1 : 0;
            int lane0 = nloc * 4 + (wKp & 3);
            sW[d][0][ntile][lane0 * 2 + reg] = wh.x;
            sW[d][0][ntile][(lane0 + 1) * 2 + reg] = wh.y;
            sW[d][1][ntile][lane0 * 2 + reg] = wl.x;
            sW[d][1][ntile][(lane0 + 1) * 2 + reg] = wl.y;
        }
        __syncthreads();
    }

    // ---- epilogue ----
    const int coff = colOffPerZ * z;
#pragma unroll
    for (int mt = 0; mt < 2; mt++) {
        int mA = m0 + wm * 32 + mt * 16 + r;
        int mB = mA + 8;
        int rA = mA, rB = mB;
        if ((flags & FLAG_FLIP) && z == 1) {
            rA = (mA & ~(SS - 1)) + ((SS - 1) - (mA & (SS - 1)));
            rB = (mB & ~(SS - 1)) + ((SS - 1) - (mB & (SS - 1)));
        }
        float* rowA = C + (size_t)z * sCz + (size_t)rA * ldc + coff;
        float* rowB = C + (size_t)z * sCz + (size_t)rB * ldc + coff;
        const float* resA = resid ? (resid + (size_t)rA * ldc + coff) : nullptr;
        const float* resB = resid ? (resid + (size_t)rB * ldc + coff) : nullptr;
#pragma unroll
        for (int nt = 0; nt < 4; nt++) {
            int n = n0 + wn * 32 + nt * 8 + 2 * c;
            float2 vA = make_float2(acc[mt][nt].x, acc[mt][nt].y);
            float2 vB = make_float2(acc[mt][nt].z, acc[mt][nt].w);
            if (bias) {
                float2 bv = *reinterpret_cast<const float2*>(&bias[z * sBiasZ + n]);
                vA.x += bv.x; vA.y += bv.y;
                vB.x += bv.x; vB.y += bv.y;
            }
            if (resA) {
                float2 qa = *reinterpret_cast<const float2*>(&resA[n]);
                float2 qb = *reinterpret_cast<const float2*>(&resB[n]);
                vA.x += qa.x; vA.y += qa.y;
                vB.x += qb.x; vB.y += qb.y;
            }
            *reinterpret_cast<float2*>(&rowA[n]) = vA;
            *reinterpret_cast<float2*>(&rowB[n]) = vB;
        }
    }
}

// ================= f32x2 fp32 GEMM (small shape: xproj N=48) =================
#define PACK_DUP(dst, s) asm("mov.b64 %0, {%1, %1};" : "=l"(dst) : "f"(s))
#define FMA2(acc, a, b)  asm("fma.rn.f32x2 %0, %1, %2, %0;" : "+l"(acc) : "l"(a), "l"(b))
#define UNPACK2(lo, hi, v) asm("mov.b64 {%0, %1}, %2;" : "=f"(lo), "=f"(hi) : "l"(v))

template<int BMT>
__global__ __launch_bounds__(256, 2) void gemm2_kernel(
    const float* __restrict__ A, int lda, long long sAz,
    const float* __restrict__ W, int ldw, long long sWz,
    float* __restrict__ C, int ldc, long long sCz, int colOffPerZ,
    const float* __restrict__ bias, int sBiasZ,
    const float* __restrict__ resid,
    int N_, int K_, int flags)
{
    constexpr int MT = BMT / 16;
    constexpr int MP = MT / 2;
    constexpr int AL = BMT + 4;
    constexpr int NA = BMT / 64;

    const int z  = blockIdx.z;
    const float* Ab = A + (size_t)z * sAz;
    const float* Wb = W + (size_t)z * sWz;
    const int m0 = blockIdx.y * BMT;
    const int n0 = blockIdx.x * 64;

    __shared__ __align__(16) float As[16][AL];
    __shared__ __align__(16) float Ws[16][68];

    unsigned long long acc[MP][4];
#pragma unroll
    for (int i = 0; i < MP; i++)
#pragma unroll
        for (int j = 0; j < 4; j++) acc[i][j] = 0ULL;

    const int tid = threadIdx.x;
    const int tx = tid & 15, ty = tid >> 4;

    float4 aFrag[NA];
    float4 wFrag;
    {
#pragma unroll
        for (int i = 0; i < NA; i++) {
            int lin = tid + i * 256;
            int m = lin >> 2, kq = (lin & 3) << 2;
            aFrag[i] = *reinterpret_cast<const float4*>(
                &Ab[(size_t)(m0 + m) * lda + kq]);
        }
        int n = tid >> 2, kq = (tid & 3) << 2;
        wFrag = make_float4(0.f, 0.f, 0.f, 0.f);
        if (n0 + n < N_)
            wFrag = *reinterpret_cast<const float4*>(
                &Wb[(size_t)(n0 + n) * ldw + kq]);
    }

    for (int k0 = 0; k0 < K_; k0 += 16) {
#pragma unroll
        for (int i = 0; i < NA; i++) {
            int lin = tid + i * 256;
            int m = lin >> 2, kq = (lin & 3) << 2;
            As[kq + 0][m] = aFrag[i].x; As[kq + 1][m] = aFrag[i].y;
            As[kq + 2][m] = aFrag[i].z; As[kq + 3][m] = aFrag[i].w;
        }
        {
            int n = tid >> 2, kq = (tid & 3) << 2;
            Ws[kq + 0][n] = wFrag.x; Ws[kq + 1][n] = wFrag.y;
            Ws[kq + 2][n] = wFrag.z; Ws[kq + 3][n] = wFrag.w;
        }
        __syncthreads();

        if (k0 + 16 < K_) {
#pragma unroll
            for (int i = 0; i < NA; i++) {
                int lin = tid + i * 256;
                int m = lin >> 2, kq = (lin & 3) << 2;
                aFrag[i] = *reinterpret_cast<const float4*>(
                    &Ab[(size_t)(m0 + m) * lda + k0 + 16 + kq]);
            }
            int n = tid >> 2, kq = (tid & 3) << 2;
            wFrag = make_float4(0.f, 0.f, 0.f, 0.f);
            if (n0 + n < N_)
                wFrag = *reinterpret_cast<const float4*>(
                    &Wb[(size_t)(n0 + n) * ldw + k0 + 16 + kq]);
        }

#pragma unroll
        for (int k = 0; k < 16; k++) {
            unsigned long long ap[MP];
            {
                ulonglong2 q0 = *reinterpret_cast<const ulonglong2*>(&As[k][ty * MT]);
                ap[0] = q0.x; ap[1] = q0.y;
                if (MP == 4) {
                    ulonglong2 q1 = *reinterpret_cast<const ulonglong2*>(&As[k][ty * MT + 4]);
                    ap[2] = q1.x; ap[3] = q1.y;
                }
            }
            float4 wv = *reinterpret_cast<const float4*>(&Ws[k][tx * 4]);
            unsigned long long wd[4];
            PACK_DUP(wd[0], wv.x); PACK_DUP(wd[1], wv.y);
            PACK_DUP(wd[2], wv.z); PACK_DUP(wd[3], wv.w);
#pragma unroll
            for (int i = 0; i < MP; i++)
#pragma unroll
                for (int j = 0; j < 4; j++)
                    FMA2(acc[i][j], ap[i], wd[j]);
        }
        __syncthreads();
    }

    const int coff = colOffPerZ * z;
#pragma unroll
    for (int i = 0; i < MP; i++) {
        int mA = m0 + ty * MT + 2 * i;
        int mB = mA + 1;
        int rA = mA, rB = mB;
        if ((flags & FLAG_FLIP) && z == 1) {
            rA = (mA & ~(SS - 1)) + ((SS - 1) - (mA & (SS - 1)));
            rB = (mB & ~(SS - 1)) + ((SS - 1) - (mB & (SS - 1)));
        }
        float* crowA = C + (size_t)z * sCz + (size_t)rA * ldc + coff;
        float* crowB = C + (size_t)z * sCz + (size_t)rB * ldc + coff;
#pragma unroll
        for (int j = 0; j < 4; j++) {
            int n = n0 + tx * 4 + j;
            if (n < N_) {
                float vA, vB;
                UNPACK2(vA, vB, acc[i][j]);
                if (bias) {
                    float bv = bias[z * sBiasZ + n];
                    vA += bv; vB += bv;
                }
                if (flags & FLAG_SOFTPLUS) {
                    vA = (vA > 20.f) ? vA : log1pf(__expf(vA));
                    vB = (vB > 20.f) ? vB : log1pf(__expf(vB));
                }
                if (resid) {
                    vA += resid[(size_t)rA * ldc + coff + n];
                    vB += resid[(size_t)rB * ldc + coff + n];
                }
                crowA[n] = vA;
                crowB[n] = vB;
            }
        }
    }
}

// ---------------- LayerNorm ----------------
__device__ __forceinline__ void block_reduce_2(float& s1, float& s2)
{
    __shared__ float sh1[8], sh2[8];
#pragma unroll
    for (int o = 16; o > 0; o >>= 1) {
        s1 += __shfl_xor_sync(0xffffffffu, s1, o);
        s2 += __shfl_xor_sync(0xffffffffu, s2, o);
    }
    int lane = threadIdx.x & 31, wid = threadIdx.x >> 5;
    if (lane == 0) { sh1[wid] = s1; sh2[wid] = s2; }
    __syncthreads();
    if (threadIdx.x == 0) {
        float a = 0.f, b = 0.f;
#pragma unroll
        for (int i = 0; i < 8; i++) { a += sh1[i]; b += sh2[i]; }
        sh1[0] = a; sh2[0] = b;
    }
    __syncthreads();
    s1 = sh1[0]; s2 = sh2[0];
}

__global__ __launch_bounds__(256) void ln_kernel(
    const float* __restrict__ src, int ldsrc, int colOffPerZ, int flipz,
    const float* __restrict__ g, const float* __restrict__ bta, int gbStrideZ,
    float* __restrict__ dst, int lddst, long long dstStrideZ, int Dvec)
{
    const int m = blockIdx.x, z = blockIdx.y;
    int srow = m;
    if (flipz && z == 1)
        srow = (m & ~(SS - 1)) + ((SS - 1) - (m & (SS - 1)));
    const float* sp = src + (size_t)srow * ldsrc + colOffPerZ * z;
    const int tid = threadIdx.x;

    float v0 = sp[tid];
    float v1 = (Dvec > 256) ? sp[tid + 256] : 0.f;
    float s1 = v0 + v1, s2 = v0 * v0 + v1 * v1;
    block_reduce_2(s1, s2);

    const float invD = 1.f / (float)Dvec;
    float mean = s1 * invD;
    float var  = s2 * invD - mean * mean;
    float inv  = rsqrtf(var + 1e-5f);

    const float* gz = g + z * gbStrideZ;
    const float* bz = bta + z * gbStrideZ;
    float* dp = dst + (size_t)z * dstStrideZ + (size_t)m * lddst;
    dp[tid] = (v0 - mean) * inv * gz[tid] + bz[tid];
    if (Dvec > 256)
        dp[tid + 256] = (v1 - mean) * inv * gz[tid + 256] + bz[tid + 256];
}

// ---------------- causal depthwise conv (K=4) + SiLU ----------------
__global__ __launch_bounds__(256) void conv_silu_kernel(
    const float* __restrict__ xz,   // [2][MM][1024], cols 0..511 are xc-raw
    const float* __restrict__ cW,   // [2][512][4]
    const float* __restrict__ cB,   // [2][512]
    float* __restrict__ xc)         // [2][MM][512]
{
    int idx = blockIdx.x * 256 + threadIdx.x;      // < 2*MM*512 = 2^21
    int d   = idx & 511;
    int row = (idx >> 9) & (MM - 1);
    int z   = idx >> 20;
    int s   = row & (SS - 1);
    int bs0 = row - s;

    const float4 wv = *reinterpret_cast<const float4*>(&cW[((size_t)z * 512 + d) * 4]);
    const float w[4] = {wv.x, wv.y, wv.z, wv.w};
    float acc = cB[z * 512 + d];
    const float* xzz = xz + (size_t)z * MM * 1024;
#pragma unroll
    for (int k = 0; k < 4; k++) {
        int sp = s - 3 + k;
        if (sp >= 0) acc += w[k] * xzz[(size_t)(bs0 + sp) * 1024 + d];
    }
    float sig = 1.f / (1.f + __expf(-acc));
    xc[(size_t)z * MM * 512 + (size_t)row * 512 + d] = acc * sig;
}

// ---------------- chunked SSM scan (dt fused: dt = softplus(dbl[:,:16]@dtW^T + dtB)) ----
__global__ __launch_bounds__(256) void scan_phase1(
    const float* __restrict__ xcp,   // [2][MM][512]
    const float* __restrict__ dblp,  // [2][MM][48]
    const float* __restrict__ A_log_l, // [2][512][16]
    const float* __restrict__ dtW_l,   // [2][512][16]
    const float* __restrict__ dtB_l,   // [2][512]
    float* __restrict__ P, float* __restrict__ hend)
{
    const int chunk = blockIdx.x >> 1;
    const int dg    = blockIdx.x & 1;
    const int b     = blockIdx.y, z = blockIdx.z;
    const int d     = dg * 256 + threadIdx.x;

    __shared__ float sIn[TCH][32];   // [t][0:16 dt-raw inputs, 16:32 B]
    const float* dbl_z = dblp + (size_t)z * MM * 48;
    const int base = b * SS + chunk * TCH;
    for (int i = threadIdx.x; i < TCH * 32; i += 256) {
        int t = i >> 5, n = i & 31;
        sIn[t][n] = dbl_z[(size_t)(base + t) * 48 + n];
    }
    __syncthreads();

    float a[NST], wdt[NST];
    const float* al = A_log_l + ((size_t)z * 512 + d) * NST;
    const float* wl = dtW_l + ((size_t)z * 512 + d) * NST;
#pragma unroll
    for (int n = 0; n < NST; n++) { a[n] = -expf(al[n]); wdt[n] = wl[n]; }
    const float bdt = dtB_l[z * 512 + d];

    float h[NST], Pr[NST];
#pragma unroll
    for (int n = 0; n < NST; n++) { h[n] = 0.f; Pr[n] = 1.f; }

    const float* xcz = xcp + (size_t)z * MM * 512;
    for (int t = 0; t < TCH; t++) {
        int row = base + t;
        float draw = bdt;
#pragma unroll
        for (int n = 0; n < NST; n++) draw = fmaf(wdt[n], sIn[t][n], draw);
        float dtv = (draw > 20.f) ? draw : log1pf(__expf(draw));
        float xv  = xcz[(size_t)row * 512 + d];
        float dx  = dtv * xv;
#pragma unroll
        for (int n = 0; n < NST; n++) {
            float dA = __expf(dtv * a[n]);
            h[n]  = fmaf(dA, h[n], dx * sIn[t][16 + n]);
            Pr[n] *= dA;
        }
    }
    size_t ob = ((((size_t)z * 2 + b) * NCH + chunk) * NST) * 512 + d;
#pragma unroll
    for (int n = 0; n < NST; n++) {
        P[ob + (size_t)n * 512]    = Pr[n];
        hend[ob + (size_t)n * 512] = h[n];
    }
}

__global__ __launch_bounds__(256) void scan_phase2(
    const float* __restrict__ P, const float* __restrict__ hend,
    float* __restrict__ hinit)
{
    int idx = blockIdx.x * 256 + threadIdx.x;   // 0..32767
    int d = idx & 511;
    int n = (idx >> 9) & 15;
    int b = (idx >> 13) & 1;
    int z = idx >> 14;
    size_t base = ((((size_t)z * 2 + b) * NCH) * NST + n) * 512 + d;
    const size_t cs = (size_t)NST * 512;

    float Pv[NCH], He[NCH];
#pragma unroll
    for (int c = 0; c < NCH; c++) {
        Pv[c] = P[base + (size_t)c * cs];
        He[c] = hend[base + (size_t)c * cs];
    }
    float h = 0.f;
#pragma unroll
    for (int c = 0; c < NCH; c++) {
        hinit[base + (size_t)c * cs] = h;
        h = fmaf(Pv[c], h, He[c]);
    }
}

__global__ __launch_bounds__(256) void scan_phase3(
    const float* __restrict__ xcp, const float* __restrict__ dblp,
    const float* __restrict__ A_log_l,
    const float* __restrict__ dtW_l, const float* __restrict__ dtB_l,
    const float* __restrict__ hinit,
    const float* __restrict__ xzp, const float* __restrict__ Dp_l,
    float* __restrict__ yg)
{
    const int chunk = blockIdx.x >> 1;
    const int dg    = blockIdx.x & 1;
    const int b     = blockIdx.y, z = blockIdx.z;
    const int d     = dg * 256 + threadIdx.x;

    __shared__ float sIn[TCH][48];   // [t][0:16 dt-in, 16:32 B, 32:48 C]
    const float* dbl_z = dblp + (size_t)z * MM * 48;
    const int base = b * SS + chunk * TCH;
    for (int i = threadIdx.x; i < TCH * 48; i += 256) {
        int t = i / 48, n = i % 48;
        sIn[t][n] = dbl_z[(size_t)(base + t) * 48 + n];
    }
    __syncthreads();

    float a[NST], wdt[NST];
    const float* al = A_log_l + ((size_t)z * 512 + d) * NST;
    const float* wl = dtW_l + ((size_t)z * 512 + d) * NST;
#pragma unroll
    for (int n = 0; n < NST; n++) { a[n] = -expf(al[n]); wdt[n] = wl[n]; }
    const float bdt = dtB_l[z * 512 + d];

    float h[NST];
    {
        size_t ob = ((((size_t)z * 2 + b) * NCH + chunk) * NST) * 512 + d;
#pragma unroll
        for (int n = 0; n < NST; n++) h[n] = hinit[ob + (size_t)n * 512];
    }
    const float Dv = Dp_l[z * 512 + d];
    const float* xcz = xcp + (size_t)z * MM * 512;
    const float* xzz = xzp + (size_t)z * MM * 1024;
    float* ygz = yg + (size_t)z * MM * 512;

    for (int t = 0; t < TCH; t++) {
        int row = base + t;
        float draw = bdt;
#pragma unroll
        for (int n = 0; n < NST; n++) draw = fmaf(wdt[n], sIn[t][n], draw);
        float dtv = (draw > 20.f) ? draw : log1pf(__expf(draw));
        float xv  = xcz[(size_t)row * 512 + d];
        float dx  = dtv * xv;
        float y = 0.f;
#pragma unroll
        for (int n = 0; n < NST; n++) {
            float dA = __expf(dtv * a[n]);
            h[n] = fmaf(dA, h[n], dx * sIn[t][16 + n]);
            y = fmaf(h[n], sIn[t][32 + n], y);
        }
        float yfull = fmaf(xv, Dv, y);
        float zv = xzz[(size_t)row * 1024 + 512 + d];
        float sig = 1.f / (1.f + __expf(-zv));
        ygz[(size_t)row * 512 + d] = yfull * zv * sig;
    }
}

// ---------------- host orchestration ----------------
extern "C" void kernel_launch(void* const* d_in, const int* in_sizes, int n_in,
                              void* d_out, int out_size)
{
    const float* x      = (const float*)d_in[0];
    const float* ln_g   = (const float*)d_in[1];
    const float* ln_b   = (const float*)d_in[2];
    const float* inW    = (const float*)d_in[3];
    const float* convW  = (const float*)d_in[4];
    const float* convB  = (const float*)d_in[5];
    const float* xprojW = (const float*)d_in[6];
    const float* dtW    = (const float*)d_in[7];
    const float* dtB    = (const float*)d_in[8];
    const float* A_log  = (const float*)d_in[9];
    const float* Dp     = (const float*)d_in[10];
    const float* outW   = (const float*)d_in[11];
    const float* ipW    = (const float*)d_in[12];
    const float* ipB    = (const float*)d_in[13];
    const float* opW    = (const float*)d_in[14];
    const float* opB    = (const float*)d_in[15];
    const float* fln_g  = (const float*)d_in[16];
    const float* fln_b  = (const float*)d_in[17];

    float* scratch = nullptr;
    cudaGetSymbolAddress((void**)&scratch, g_scratch);
    float* xp   = scratch + OFF_XP;
    float* xn   = scratch + OFF_XN;
    float* xzb  = scratch + OFF_XZ;
    float* xc   = scratch + OFF_XC;
    float* dbl  = scratch + OFF_DBL;
    float* yg   = scratch + OFF_YG;
    float* ycat = scratch + OFF_YCAT;
    float* hbuf[2] = { scratch + OFF_H0, scratch + OFF_H1 };
    float* Pb   = scratch + OFF_P;
    float* heb  = scratch + OFF_HEND;
    float* hib  = scratch + OFF_HINIT;

    uint32_t* wpk = (uint32_t*)(scratch + OFF_WPK);
    uint32_t* ipH = wpk + WPK_IP;  uint32_t* ipL = wpk + WPK_HALF + WPK_IP;
    uint32_t* inH = wpk + WPK_IN;  uint32_t* inL = wpk + WPK_HALF + WPK_IN;
    uint32_t* otH = wpk + WPK_OUT; uint32_t* otL = wpk + WPK_HALF + WPK_OUT;
    uint32_t* opH = wpk + WPK_OP;  uint32_t* opL = wpk + WPK_HALF + WPK_OP;

    // ---- pre-split all weights into packed bf16 hi/lo (single launch) ----
    pack_all_kernel<<<(WPK_HALF + 255) / 256, 256>>>(
        ipW, inW, outW, opW, wpk, wpk + WPK_HALF);

    const float* hin = x;
    for (int l = 0; l < LNUM; l++) {
        const size_t l2 = (size_t)l * 2;

        // xp = hin @ ipW_l^T + ipB_l          (M=2048, N=512, K=512) — tensor
        gemm_bf16_kernel<<<dim3(8, 16, 1), 256>>>(
            hin, 512, 0, ipH + (size_t)l * 131072, ipL + (size_t)l * 131072, 256, 0,
            xp, 512, 0, 0, ipB + l * 512, 0, nullptr, 512, 0);

        // per-dir LN over 256 (dir1 reads cols 256.. with flipped S)
        ln_kernel<<<dim3(MM, 2), 256>>>(
            xp, 512, 256, 1, ln_g + l2 * 256, ln_b + l2 * 256, 256,
            xn, 256, (long long)MM * 256, 256);

        // xz = xn @ inW^T                      (N=1024, K=256), both dirs — tensor
        gemm_bf16_kernel<<<dim3(16, 16, 2), 256>>>(
            xn, 256, (long long)MM * 256,
            inH + l2 * 131072, inL + l2 * 131072, 128, 131072,
            xzb, 1024, (long long)MM * 1024, 0, nullptr, 0, nullptr, 256, 0);

        // causal dwconv + silu on xz[..,:512]
        conv_silu_kernel<<<(2 * MM * 512) / 256, 256>>>(
            xzb, convW + l2 * 512 * 4, convB + l2 * 512, xc);

        // dbl = xc @ xprojW^T                  (N=48, K=512) — fp32
        gemm2_kernel<64><<<dim3(1, 32, 2), 256>>>(
            xc, 512, (long long)MM * 512,
            xprojW + l2 * 48 * 512, 512, (long long)48 * 512,
            dbl, 48, (long long)MM * 48, 0, nullptr, 0, nullptr, 48, 512, 0);

        // chunked scan (dt computed in-kernel from dbl + dtW + dtB)
        scan_phase1<<<dim3(NCH * 2, 2, 2), 256>>>(
            xc, dbl, A_log + l2 * 512 * NST,
            dtW + l2 * 512 * NST, dtB + l2 * 512, Pb, heb);
        scan_phase2<<<128, 256>>>(Pb, heb, hib);
        scan_phase3<<<dim3(NCH * 2, 2, 2), 256>>>(
            xc, dbl, A_log + l2 * 512 * NST,
            dtW + l2 * 512 * NST, dtB + l2 * 512,
            hib, xzb, Dp + l2 * 512, yg);

        // ycat[:, z*256..] = u + yg @ outW^T   (N=256, K=512), dir1 flip-store — tensor
        gemm_bf16_kernel<<<dim3(4, 16, 2), 256>>>(
            yg, 512, (long long)MM * 512,
            otH + l2 * 65536, otL + l2 * 65536, 256, 65536,
            ycat, 512, 0, 256, nullptr, 0, xp, 512, FLAG_FLIP);

        // h_next = ycat @ opW^T + opB          (N=512, K=512) — tensor
        float* hout = hbuf[l & 1];
        gemm_bf16_kernel<<<dim3(8, 16, 1), 256>>>(
            ycat, 512, 0, opH + (size_t)l * 131072, opL + (size_t)l * 131072, 256, 0,
            hout, 512, 0, 0, opB + l * 512, 0, nullptr, 512, 0);
        hin = hout;
    }

    // final LN over 512 -> d_out
    ln_kernel<<<dim3(MM, 1), 256>>>(
        hin, 512, 0, 0, fln_g, fln_b, 0,
        (float*)d_out, 512, 0, 512);
}

// round 8
// speedup vs baseline: 2.0221x; 1.0849x over previous
#include <cuda_runtime.h>
#include <cuda_bf16.h>
#include <cstdint>

// Problem constants
#define LNUM 2
#define SS   1024
#define MM   2048      // B*S tokens
#define NST  16        // SSM state dim
#define NCH  32        // scan chunks
#define TCH  32        // steps per chunk

#define FLAG_FLIP     2

// ---------------- scratch (static device memory; no allocation) ----------------
#define OFF_XP    0
#define OFF_XN    (OFF_XP   + MM*512)
#define OFF_XZ    (OFF_XN   + 2*MM*256)
#define OFF_XC    (OFF_XZ   + 2*MM*1024)
#define OFF_DBL   (OFF_XC   + 2*MM*512)
#define OFF_YG    (OFF_DBL  + 2*MM*48)
#define OFF_YCAT  (OFF_YG   + 2*MM*512)
#define OFF_H0    (OFF_YCAT + MM*512)
#define OFF_H1    (OFF_H0   + MM*512)
#define OFF_P     (OFF_H1   + MM*512)
#define OFF_HEND  (OFF_P    + 2*2*NCH*NST*512)
#define OFF_HINIT (OFF_HEND + 2*2*NCH*NST*512)
// packed bf16 hi/lo weights (uint32 words stored in float slots)
#define OFF_WPK   (OFF_HINIT + 2*2*NCH*NST*512)
#define WPK_IP    0
#define WPK_IN    (WPK_IP  + 262144)
#define WPK_OUT   (WPK_IN  + 524288)
#define WPK_OP    (WPK_OUT + 262144)
#define WPK_XP    (WPK_OP  + 262144)     // xprojW padded to 64 rows
#define WPK_HALF  (WPK_XP  + 65536)
#define SCRATCH_TOTAL (OFF_WPK + 2*WPK_HALF)

__device__ float g_scratch[SCRATCH_TOTAL];

// ---------------- bf16 split helpers ----------------
__device__ __forceinline__ uint32_t cvt_pack_bf16(float up, float lo) {
    uint32_t r;
    asm("cvt.rn.bf16x2.f32 %0, %1, %2;" : "=r"(r) : "f"(up), "f"(lo));
    return r;
}
// split pair (e0 = lower half / smaller k, e1 = upper half)
__device__ __forceinline__ void split_pair(float e0, float e1, uint32_t& h, uint32_t& l) {
    h = cvt_pack_bf16(e1, e0);
    float h0 = __uint_as_float(h << 16);
    float h1 = __uint_as_float(h & 0xffff0000u);
    l = cvt_pack_bf16(e1 - h1, e0 - h0);
}

__device__ __forceinline__ void mma_bf16(float4& c, const uint32_t a[4], const uint32_t b[2]) {
    asm volatile(
        "mma.sync.aligned.m16n8k16.row.col.f32.bf16.bf16.f32 "
        "{%0,%1,%2,%3}, {%4,%5,%6,%7}, {%8,%9}, {%0,%1,%2,%3};"
        : "+f"(c.x), "+f"(c.y), "+f"(c.z), "+f"(c.w)
        : "r"(a[0]), "r"(a[1]), "r"(a[2]), "r"(a[3]), "r"(b[0]), "r"(b[1]));
}

__device__ __forceinline__ void ldsm_x4(uint32_t& r0, uint32_t& r1, uint32_t& r2,
                                        uint32_t& r3, uint32_t addr) {
    asm volatile("ldmatrix.sync.aligned.m8n8.x4.shared.b16 {%0,%1,%2,%3}, [%4];"
                 : "=r"(r0), "=r"(r1), "=r"(r2), "=r"(r3) : "r"(addr));
}

__device__ __forceinline__ uint32_t smaddr(const void* p) {
    return static_cast<uint32_t>(__cvta_generic_to_shared(p));
}

// ---------------- merged weight pre-pack (5 regions, xproj zero-padded) ----------------
__global__ __launch_bounds__(256) void pack_all_kernel(
    const float* __restrict__ ipW, const float* __restrict__ inW,
    const float* __restrict__ outW, const float* __restrict__ opW,
    const float* __restrict__ xprojW,
    uint32_t* __restrict__ dstHi, uint32_t* __restrict__ dstLo)
{
    int i = blockIdx.x * 256 + threadIdx.x;
    if (i >= WPK_HALF) return;
    float2 v;
    if (i < WPK_XP) {
        const float* src;
        int local;
        if (i < WPK_IN)       { src = ipW;  local = i - WPK_IP; }
        else if (i < WPK_OUT) { src = inW;  local = i - WPK_IN; }
        else if (i < WPK_OP)  { src = outW; local = i - WPK_OUT; }
        else                  { src = opW;  local = i - WPK_OP; }
        v = *reinterpret_cast<const float2*>(&src[2 * local]);
    } else {
        int q = i - WPK_XP;                // [0, 65536)
        int ldir = q >> 14;                // 0..3
        int rem = q & 16383;
        int row = rem >> 8;                // 0..63
        int wp = rem & 255;
        if (row < 48)
            v = *reinterpret_cast<const float2*>(
                &xprojW[((size_t)ldir * 48 + row) * 512 + wp * 2]);
        else
            v = make_float2(0.f, 0.f);
    }
    uint32_t h, l;
    split_pair(v.x, v.y, h, l);
    dstHi[i] = h;
    dstLo[i] = l;
}

// ================= bf16-split mma.sync GEMM (ldmatrix layout) =================
// C = A(M x K) @ W(N_pad x K)^T (+bias)(+resid, flip-store)
// Block 128 x 64, BK=16, 256 threads (8 warps: 4m x 2n), warp tile 32x32.
// Smem: bf16 rows, 32B/row, XOR swizzle on 16B-half index by (row>>2)&1.
// D = Ah*Bh + Ah*Bl + Al*Bh  (fp32 accumulation)
__global__ __launch_bounds__(256, 2) void gemm_bf16_kernel(
    const float* __restrict__ A, int lda, long long sAz,
    const uint32_t* __restrict__ Whi, const uint32_t* __restrict__ Wlo,
    int ldwp, int sWzp,
    float* __restrict__ C, int ldc, long long sCz, int colOffPerZ,
    const float* __restrict__ bias, int sBiasZ,
    const float* __restrict__ resid,
    int N_, int K_, int flags)
{
    // [buf][mat(hi/lo)] planes of bf16 rows (32B each)
    __shared__ __align__(16) unsigned char sAb[2][2][128 * 32];
    __shared__ __align__(16) unsigned char sWb[2][2][64 * 32];

    const int tid = threadIdx.x;
    const int wid = tid >> 5, lane = tid & 31;
    const int wm = wid >> 1, wn = wid & 1;   // warp grid 4m x 2n
    const int r = lane >> 2, c = lane & 3;

    const int z = blockIdx.z;
    const int m0 = blockIdx.y * 128, n0 = blockIdx.x * 64;
    const float* Ab = A + (size_t)z * sAz;
    const uint32_t* WhiZ = Whi + (size_t)z * sWzp;
    const uint32_t* WloZ = Wlo + (size_t)z * sWzp;

    const uint32_t sA_base = smaddr(&sAb[0][0][0]);
    const uint32_t sW_base = smaddr(&sWb[0][0][0]);

    float4 acc[2][4];
#pragma unroll
    for (int i = 0; i < 2; i++)
#pragma unroll
        for (int j = 0; j < 4; j++) acc[i][j] = make_float4(0.f, 0.f, 0.f, 0.f);

    const int NC = K_ >> 4;

    // staging
    float4 ar[2];
    uint2 wh, wl;
    const int aRow = tid >> 2, aKq = (tid & 3) << 2;     // + i*64 rows, kq in {0,4,8,12}
    const int wN = tid >> 2, wKp = (tid & 3) * 2;        // word pair base {0,2,4,6}

    // precomputed store offsets (swizzled)
    const int aHalf0 = (aKq >> 3);
    const int wKb = wKp * 4;                              // {0,8,16,24}
    const int wHalf = (wKb >> 4) ^ ((wN >> 2) & 1);
    const int wOff = wN * 32 + wHalf * 16 + (wKb & 8);

    // ---- load chunk 0 ----
#pragma unroll
    for (int i = 0; i < 2; i++)
        ar[i] = *reinterpret_cast<const float4*>(&Ab[(size_t)(m0 + aRow + i * 64) * lda + aKq]);
    wh = *reinterpret_cast<const uint2*>(&WhiZ[(size_t)(n0 + wN) * ldwp + wKp]);
    wl = *reinterpret_cast<const uint2*>(&WloZ[(size_t)(n0 + wN) * ldwp + wKp]);

    // ---- store chunk 0 into buf 0 ----
    {
#pragma unroll
        for (int i = 0; i < 2; i++) {
            int row = aRow + i * 64;
            int half = aHalf0 ^ ((row >> 2) & 1);
            int off = row * 32 + half * 16 + (aKq & 7) * 2;
            uint32_t h01, l01, h23, l23;
            split_pair(ar[i].x, ar[i].y, h01, l01);
            split_pair(ar[i].z, ar[i].w, h23, l23);
            *reinterpret_cast<uint2*>(&sAb[0][0][off]) = make_uint2(h01, h23);
            *reinterpret_cast<uint2*>(&sAb[0][1][off]) = make_uint2(l01, l23);
        }
        *reinterpret_cast<uint2*>(&sWb[0][0][wOff]) = make_uint2(wh.x, wh.y);
        *reinterpret_cast<uint2*>(&sWb[0][1][wOff]) = make_uint2(wl.x, wl.y);
    }
    __syncthreads();

    for (int cc = 0; cc < NC; cc++) {
        const int s = cc & 1;

        // ---- prefetch chunk cc+1 into regs ----
        if (cc + 1 < NC) {
            const int kb = (cc + 1) * 16;
            const int pb = (cc + 1) * 8;
#pragma unroll
            for (int i = 0; i < 2; i++)
                ar[i] = *reinterpret_cast<const float4*>(
                    &Ab[(size_t)(m0 + aRow + i * 64) * lda + kb + aKq]);
            wh = *reinterpret_cast<const uint2*>(&WhiZ[(size_t)(n0 + wN) * ldwp + pb + wKp]);
            wl = *reinterpret_cast<const uint2*>(&WloZ[(size_t)(n0 + wN) * ldwp + pb + wKp]);
        }

        // ---- compute from buf s via ldmatrix ----
        {
            uint32_t ah[2][4], al[2][4], bh[4][2], bl[4][2];
            // A: mtiles wm*2, wm*2+1; matrices (r0-7,k0-7),(r8-15,k0-7),(r0-7,k8-15),(r8-15,k8-15)
            const int mrow_in = ((lane >> 3) & 1) * 8 + (lane & 7);
            const int akh = lane >> 4;
#pragma unroll
            for (int mt = 0; mt < 2; mt++) {
                int mrow = (wm * 2 + mt) * 16 + mrow_in;
                int half = akh ^ ((mrow >> 2) & 1);
                uint32_t off = (uint32_t)(mrow * 32 + half * 16);
                ldsm_x4(ah[mt][0], ah[mt][1], ah[mt][2], ah[mt][3],
                        sA_base + (s * 2 + 0) * 4096 + off);
                ldsm_x4(al[mt][0], al[mt][1], al[mt][2], al[mt][3],
                        sA_base + (s * 2 + 1) * 4096 + off);
            }
            // B: ntile pairs; matrices (nt,k0-7),(nt,k8-15),(nt+1,k0-7),(nt+1,k8-15)
            const int bkh = (lane >> 3) & 1;
#pragma unroll
            for (int p = 0; p < 2; p++) {
                int ntile = wn * 4 + p * 2 + (lane >> 4);
                int nrow = ntile * 8 + (lane & 7);
                int half = bkh ^ ((nrow >> 2) & 1);
                uint32_t off = (uint32_t)(nrow * 32 + half * 16);
                ldsm_x4(bh[p * 2][0], bh[p * 2][1], bh[p * 2 + 1][0], bh[p * 2 + 1][1],
                        sW_base + (s * 2 + 0) * 2048 + off);
                ldsm_x4(bl[p * 2][0], bl[p * 2][1], bl[p * 2 + 1][0], bl[p * 2 + 1][1],
                        sW_base + (s * 2 + 1) * 2048 + off);
            }
#pragma unroll
            for (int mt = 0; mt < 2; mt++)
#pragma unroll
                for (int nt = 0; nt < 4; nt++) {
                    mma_bf16(acc[mt][nt], ah[mt], bh[nt]);
                    mma_bf16(acc[mt][nt], al[mt], bh[nt]);
                    mma_bf16(acc[mt][nt], ah[mt], bl[nt]);
                }
        }

        // ---- store prefetched chunk into other buffer ----
        if (cc + 1 < NC) {
            const int d = s ^ 1;
#pragma unroll
            for (int i = 0; i < 2; i++) {
                int row = aRow + i * 64;
                int half = aHalf0 ^ ((row >> 2) & 1);
                int off = row * 32 + half * 16 + (aKq & 7) * 2;
                uint32_t h01, l01, h23, l23;
                split_pair(ar[i].x, ar[i].y, h01, l01);
                split_pair(ar[i].z, ar[i].w, h23, l23);
                *reinterpret_cast<uint2*>(&sAb[d][0][off]) = make_uint2(h01, h23);
                *reinterpret_cast<uint2*>(&sAb[d][1][off]) = make_uint2(l01, l23);
            }
            *reinterpret_cast<uint2*>(&sWb[d][0][wOff]) = make_uint2(wh.x, wh.y);
            *reinterpret_cast<uint2*>(&sWb[d][1][wOff]) = make_uint2(wl.x, wl.y);
        }
        __syncthreads();
    }

    // ---- epilogue ----
    const int coff = colOffPerZ * z;
#pragma unroll
    for (int mt = 0; mt < 2; mt++) {
        int mA = m0 + wm * 32 + mt * 16 + r;
        int mB = mA + 8;
        int rA = mA, rB = mB;
        if ((flags & FLAG_FLIP) && z == 1) {
            rA = (mA & ~(SS - 1)) + ((SS - 1) - (mA & (SS - 1)));
            rB = (mB & ~(SS - 1)) + ((SS - 1) - (mB & (SS - 1)));
        }
        float* rowA = C + (size_t)z * sCz + (size_t)rA * ldc + coff;
        float* rowB = C + (size_t)z * sCz + (size_t)rB * ldc + coff;
        const float* resA = resid ? (resid + (size_t)rA * ldc + coff) : nullptr;
        const float* resB = resid ? (resid + (size_t)rB * ldc + coff) : nullptr;
#pragma unroll
        for (int nt = 0; nt < 4; nt++) {
            int n = n0 + wn * 32 + nt * 8 + 2 * c;
            if (n >= N_) continue;
            float2 vA = make_float2(acc[mt][nt].x, acc[mt][nt].y);
            float2 vB = make_float2(acc[mt][nt].z, acc[mt][nt].w);
            if (bias) {
                float2 bv = *reinterpret_cast<const float2*>(&bias[z * sBiasZ + n]);
                vA.x += bv.x; vA.y += bv.y;
                vB.x += bv.x; vB.y += bv.y;
            }
            if (resA) {
                float2 qa = *reinterpret_cast<const float2*>(&resA[n]);
                float2 qb = *reinterpret_cast<const float2*>(&resB[n]);
                vA.x += qa.x; vA.y += qa.y;
                vB.x += qb.x; vB.y += qb.y;
            }
            *reinterpret_cast<float2*>(&rowA[n]) = vA;
            *reinterpret_cast<float2*>(&rowB[n]) = vB;
        }
    }
}

// ---------------- LayerNorm ----------------
__device__ __forceinline__ void block_reduce_2(float& s1, float& s2)
{
    __shared__ float sh1[8], sh2[8];
#pragma unroll
    for (int o = 16; o > 0; o >>= 1) {
        s1 += __shfl_xor_sync(0xffffffffu, s1, o);
        s2 += __shfl_xor_sync(0xffffffffu, s2, o);
    }
    int lane = threadIdx.x & 31, wid = threadIdx.x >> 5;
    if (lane == 0) { sh1[wid] = s1; sh2[wid] = s2; }
    __syncthreads();
    if (threadIdx.x == 0) {
        float a = 0.f, b = 0.f;
#pragma unroll
        for (int i = 0; i < 8; i++) { a += sh1[i]; b += sh2[i]; }
        sh1[0] = a; sh2[0] = b;
    }
    __syncthreads();
    s1 = sh1[0]; s2 = sh2[0];
}

__global__ __launch_bounds__(256) void ln_kernel(
    const float* __restrict__ src, int ldsrc, int colOffPerZ, int flipz,
    const float* __restrict__ g, const float* __restrict__ bta, int gbStrideZ,
    float* __restrict__ dst, int lddst, long long dstStrideZ, int Dvec)
{
    const int m = blockIdx.x, z = blockIdx.y;
    int srow = m;
    if (flipz && z == 1)
        srow = (m & ~(SS - 1)) + ((SS - 1) - (m & (SS - 1)));
    const float* sp = src + (size_t)srow * ldsrc + colOffPerZ * z;
    const int tid = threadIdx.x;

    float v0 = sp[tid];
    float v1 = (Dvec > 256) ? sp[tid + 256] : 0.f;
    float s1 = v0 + v1, s2 = v0 * v0 + v1 * v1;
    block_reduce_2(s1, s2);

    const float invD = 1.f / (float)Dvec;
    float mean = s1 * invD;
    float var  = s2 * invD - mean * mean;
    float inv  = rsqrtf(var + 1e-5f);

    const float* gz = g + z * gbStrideZ;
    const float* bz = bta + z * gbStrideZ;
    float* dp = dst + (size_t)z * dstStrideZ + (size_t)m * lddst;
    dp[tid] = (v0 - mean) * inv * gz[tid] + bz[tid];
    if (Dvec > 256)
        dp[tid + 256] = (v1 - mean) * inv * gz[tid + 256] + bz[tid + 256];
}

// ---------------- causal depthwise conv (K=4) + SiLU ----------------
__global__ __launch_bounds__(256) void conv_silu_kernel(
    const float* __restrict__ xz,   // [2][MM][1024], cols 0..511 are xc-raw
    const float* __restrict__ cW,   // [2][512][4]
    const float* __restrict__ cB,   // [2][512]
    float* __restrict__ xc)         // [2][MM][512]
{
    int idx = blockIdx.x * 256 + threadIdx.x;      // < 2*MM*512 = 2^21
    int d   = idx & 511;
    int row = (idx >> 9) & (MM - 1);
    int z   = idx >> 20;
    int s   = row & (SS - 1);
    int bs0 = row - s;

    const float4 wv = *reinterpret_cast<const float4*>(&cW[((size_t)z * 512 + d) * 4]);
    const float w[4] = {wv.x, wv.y, wv.z, wv.w};
    float acc = cB[z * 512 + d];
    const float* xzz = xz + (size_t)z * MM * 1024;
#pragma unroll
    for (int k = 0; k < 4; k++) {
        int sp = s - 3 + k;
        if (sp >= 0) acc += w[k] * xzz[(size_t)(bs0 + sp) * 1024 + d];
    }
    float sig = 1.f / (1.f + __expf(-acc));
    xc[(size_t)z * MM * 512 + (size_t)row * 512 + d] = acc * sig;
}

// ---------------- chunked SSM scan (dt fused: dt = softplus(dbl[:,:16]@dtW^T + dtB)) ----
__global__ __launch_bounds__(256) void scan_phase1(
    const float* __restrict__ xcp,   // [2][MM][512]
    const float* __restrict__ dblp,  // [2][MM][48]
    const float* __restrict__ A_log_l, // [2][512][16]
    const float* __restrict__ dtW_l,   // [2][512][16]
    const float* __restrict__ dtB_l,   // [2][512]
    float* __restrict__ P, float* __restrict__ hend)
{
    const int chunk = blockIdx.x >> 1;
    const int dg    = blockIdx.x & 1;
    const int b     = blockIdx.y, z = blockIdx.z;
    const int d     = dg * 256 + threadIdx.x;

    __shared__ float sIn[TCH][32];   // [t][0:16 dt-raw inputs, 16:32 B]
    const float* dbl_z = dblp + (size_t)z * MM * 48;
    const int base = b * SS + chunk * TCH;
    for (int i = threadIdx.x; i < TCH * 32; i += 256) {
        int t = i >> 5, n = i & 31;
        sIn[t][n] = dbl_z[(size_t)(base + t) * 48 + n];
    }
    __syncthreads();

    float a[NST], wdt[NST];
    const float* al = A_log_l + ((size_t)z * 512 + d) * NST;
    const float* wl = dtW_l + ((size_t)z * 512 + d) * NST;
#pragma unroll
    for (int n = 0; n < NST; n++) { a[n] = -expf(al[n]); wdt[n] = wl[n]; }
    const float bdt = dtB_l[z * 512 + d];

    float h[NST], Pr[NST];
#pragma unroll
    for (int n = 0; n < NST; n++) { h[n] = 0.f; Pr[n] = 1.f; }

    const float* xcz = xcp + (size_t)z * MM * 512;
    for (int t = 0; t < TCH; t++) {
        int row = base + t;
        float draw = bdt;
#pragma unroll
        for (int n = 0; n < NST; n++) draw = fmaf(wdt[n], sIn[t][n], draw);
        float dtv = (draw > 20.f) ? draw : log1pf(__expf(draw));
        float xv  = xcz[(size_t)row * 512 + d];
        float dx  = dtv * xv;
#pragma unroll
        for (int n = 0; n < NST; n++) {
            float dA = __expf(dtv * a[n]);
            h[n]  = fmaf(dA, h[n], dx * sIn[t][16 + n]);
            Pr[n] *= dA;
        }
    }
    size_t ob = ((((size_t)z * 2 + b) * NCH + chunk) * NST) * 512 + d;
#pragma unroll
    for (int n = 0; n < NST; n++) {
        P[ob + (size_t)n * 512]    = Pr[n];
        hend[ob + (size_t)n * 512] = h[n];
    }
}

__global__ __launch_bounds__(256) void scan_phase2(
    const float* __restrict__ P, const float* __restrict__ hend,
    float* __restrict__ hinit)
{
    int idx = blockIdx.x * 256 + threadIdx.x;   // 0..32767
    int d = idx & 511;
    int n = (idx >> 9) & 15;
    int b = (idx >> 13) & 1;
    int z = idx >> 14;
    size_t base = ((((size_t)z * 2 + b) * NCH) * NST + n) * 512 + d;
    const size_t cs = (size_t)NST * 512;

    float Pv[NCH], He[NCH];
#pragma unroll
    for (int c = 0; c < NCH; c++) {
        Pv[c] = P[base + (size_t)c * cs];
        He[c] = hend[base + (size_t)c * cs];
    }
    float h = 0.f;
#pragma unroll
    for (int c = 0; c < NCH; c++) {
        hinit[base + (size_t)c * cs] = h;
        h = fmaf(Pv[c], h, He[c]);
    }
}

__global__ __launch_bounds__(256) void scan_phase3(
    const float* __restrict__ xcp, const float* __restrict__ dblp,
    const float* __restrict__ A_log_l,
    const float* __restrict__ dtW_l, const float* __restrict__ dtB_l,
    const float* __restrict__ hinit,
    const float* __restrict__ xzp, const float* __restrict__ Dp_l,
    float* __restrict__ yg)
{
    const int chunk = blockIdx.x >> 1;
    const int dg    = blockIdx.x & 1;
    const int b     = blockIdx.y, z = blockIdx.z;
    const int d     = dg * 256 + threadIdx.x;

    __shared__ float sIn[TCH][48];   // [t][0:16 dt-in, 16:32 B, 32:48 C]
    const float* dbl_z = dblp + (size_t)z * MM * 48;
    const int base = b * SS + chunk * TCH;
    for (int i = threadIdx.x; i < TCH * 48; i += 256) {
        int t = i / 48, n = i % 48;
        sIn[t][n] = dbl_z[(size_t)(base + t) * 48 + n];
    }
    __syncthreads();

    float a[NST], wdt[NST];
    const float* al = A_log_l + ((size_t)z * 512 + d) * NST;
    const float* wl = dtW_l + ((size_t)z * 512 + d) * NST;
#pragma unroll
    for (int n = 0; n < NST; n++) { a[n] = -expf(al[n]); wdt[n] = wl[n]; }
    const float bdt = dtB_l[z * 512 + d];

    float h[NST];
    {
        size_t ob = ((((size_t)z * 2 + b) * NCH + chunk) * NST) * 512 + d;
#pragma unroll
        for (int n = 0; n < NST; n++) h[n] = hinit[ob + (size_t)n * 512];
    }
    const float Dv = Dp_l[z * 512 + d];
    const float* xcz = xcp + (size_t)z * MM * 512;
    const float* xzz = xzp + (size_t)z * MM * 1024;
    float* ygz = yg + (size_t)z * MM * 512;

    for (int t = 0; t < TCH; t++) {
        int row = base + t;
        float draw = bdt;
#pragma unroll
        for (int n = 0; n < NST; n++) draw = fmaf(wdt[n], sIn[t][n], draw);
        float dtv = (draw > 20.f) ? draw : log1pf(__expf(draw));
        float xv  = xcz[(size_t)row * 512 + d];
        float dx  = dtv * xv;
        float y = 0.f;
#pragma unroll
        for (int n = 0; n < NST; n++) {
            float dA = __expf(dtv * a[n]);
            h[n] = fmaf(dA, h[n], dx * sIn[t][16 + n]);
            y = fmaf(h[n], sIn[t][32 + n], y);
        }
        float yfull = fmaf(xv, Dv, y);
        float zv = xzz[(size_t)row * 1024 + 512 + d];
        float sig = 1.f / (1.f + __expf(-zv));
        ygz[(size_t)row * 512 + d] = yfull * zv * sig;
    }
}

// ---------------- host orchestration ----------------
extern "C" void kernel_launch(void* const* d_in, const int* in_sizes, int n_in,
                              void* d_out, int out_size)
{
    const float* x      = (const float*)d_in[0];
    const float* ln_g   = (const float*)d_in[1];
    const float* ln_b   = (const float*)d_in[2];
    const float* inW    = (const float*)d_in[3];
    const float* convW  = (const float*)d_in[4];
    const float* convB  = (const float*)d_in[5];
    const float* xprojW = (const float*)d_in[6];
    const float* dtW    = (const float*)d_in[7];
    const float* dtB    = (const float*)d_in[8];
    const float* A_log  = (const float*)d_in[9];
    const float* Dp     = (const float*)d_in[10];
    const float* outW   = (const float*)d_in[11];
    const float* ipW    = (const float*)d_in[12];
    const float* ipB    = (const float*)d_in[13];
    const float* opW    = (const float*)d_in[14];
    const float* opB    = (const float*)d_in[15];
    const float* fln_g  = (const float*)d_in[16];
    const float* fln_b  = (const float*)d_in[17];

    float* scratch = nullptr;
    cudaGetSymbolAddress((void**)&scratch, g_scratch);
    float* xp   = scratch + OFF_XP;
    float* xn   = scratch + OFF_XN;
    float* xzb  = scratch + OFF_XZ;
    float* xc   = scratch + OFF_XC;
    float* dbl  = scratch + OFF_DBL;
    float* yg   = scratch + OFF_YG;
    float* ycat = scratch + OFF_YCAT;
    float* hbuf[2] = { scratch + OFF_H0, scratch + OFF_H1 };
    float* Pb   = scratch + OFF_P;
    float* heb  = scratch + OFF_HEND;
    float* hib  = scratch + OFF_HINIT;

    uint32_t* wpk = (uint32_t*)(scratch + OFF_WPK);
    uint32_t* ipH = wpk + WPK_IP;  uint32_t* ipL = wpk + WPK_HALF + WPK_IP;
    uint32_t* inH = wpk + WPK_IN;  uint32_t* inL = wpk + WPK_HALF + WPK_IN;
    uint32_t* otH = wpk + WPK_OUT; uint32_t* otL = wpk + WPK_HALF + WPK_OUT;
    uint32_t* opH = wpk + WPK_OP;  uint32_t* opL = wpk + WPK_HALF + WPK_OP;
    uint32_t* xpH = wpk + WPK_XP;  uint32_t* xpL = wpk + WPK_HALF + WPK_XP;

    // ---- pre-split all weights into packed bf16 hi/lo (single launch) ----
    pack_all_kernel<<<(WPK_HALF + 255) / 256, 256>>>(
        ipW, inW, outW, opW, xprojW, wpk, wpk + WPK_HALF);

    const float* hin = x;
    for (int l = 0; l < LNUM; l++) {
        const size_t l2 = (size_t)l * 2;

        // xp = hin @ ipW_l^T + ipB_l          (M=2048, N=512, K=512) — tensor
        gemm_bf16_kernel<<<dim3(8, 16, 1), 256>>>(
            hin, 512, 0, ipH + (size_t)l * 131072, ipL + (size_t)l * 131072, 256, 0,
            xp, 512, 0, 0, ipB + l * 512, 0, nullptr, 512, 512, 0);

        // per-dir LN over 256 (dir1 reads cols 256.. with flipped S)
        ln_kernel<<<dim3(MM, 2), 256>>>(
            xp, 512, 256, 1, ln_g + l2 * 256, ln_b + l2 * 256, 256,
            xn, 256, (long long)MM * 256, 256);

        // xz = xn @ inW^T                      (N=1024, K=256), both dirs — tensor
        gemm_bf16_kernel<<<dim3(16, 16, 2), 256>>>(
            xn, 256, (long long)MM * 256,
            inH + l2 * 131072, inL + l2 * 131072, 128, 131072,
            xzb, 1024, (long long)MM * 1024, 0, nullptr, 0, nullptr, 1024, 256, 0);

        // causal dwconv + silu on xz[..,:512]
        conv_silu_kernel<<<(2 * MM * 512) / 256, 256>>>(
            xzb, convW + l2 * 512 * 4, convB + l2 * 512, xc);

        // dbl = xc @ xprojW^T                  (N=48 padded to 64, K=512) — tensor
        gemm_bf16_kernel<<<dim3(1, 16, 2), 256>>>(
            xc, 512, (long long)MM * 512,
            xpH + l2 * 16384, xpL + l2 * 16384, 256, 16384,
            dbl, 48, (long long)MM * 48, 0, nullptr, 0, nullptr, 48, 512, 0);

        // chunked scan (dt computed in-kernel from dbl + dtW + dtB)
        scan_phase1<<<dim3(NCH * 2, 2, 2), 256>>>(
            xc, dbl, A_log + l2 * 512 * NST,
            dtW + l2 * 512 * NST, dtB + l2 * 512, Pb, heb);
        scan_phase2<<<128, 256>>>(Pb, heb, hib);
        scan_phase3<<<dim3(NCH * 2, 2, 2), 256>>>(
            xc, dbl, A_log + l2 * 512 * NST,
            dtW + l2 * 512 * NST, dtB + l2 * 512,
            hib, xzb, Dp + l2 * 512, yg);

        // ycat[:, z*256..] = u + yg @ outW^T   (N=256, K=512), dir1 flip-store — tensor
        gemm_bf16_kernel<<<dim3(4, 16, 2), 256>>>(
            yg, 512, (long long)MM * 512,
            otH + l2 * 65536, otL + l2 * 65536, 256, 65536,
            ycat, 512, 0, 256, nullptr, 0, xp, 256, 512, FLAG_FLIP);

        // h_next = ycat @ opW^T + opB          (N=512, K=512) — tensor
        float* hout = hbuf[l & 1];
        gemm_bf16_kernel<<<dim3(8, 16, 1), 256>>>(
            ycat, 512, 0, opH + (size_t)l * 131072, opL + (size_t)l * 131072, 256, 0,
            hout, 512, 0, 0, opB + l * 512, 0, nullptr, 512, 512, 0);
        hin = hout;
    }

    // final LN over 512 -> d_out
    ln_kernel<<<dim3(MM, 1), 256>>>(
        hin, 512, 0, 0, fln_g, fln_b, 0,
        (float*)d_out, 512, 0, 512);
}